// round 1
// baseline (speedup 1.0000x reference)
#include <cuda_runtime.h>
#include <math.h>

#define SDIM 1024
#define EDIM 1024
#define BDIM 4
#define HDIM 16
#define DDIM 64
#define BH   64          // BDIM*HDIM
#define MTOT 4096        // BDIM*SDIM

// ---------------- scratch (device globals; no allocation) ----------------
__device__ float g_p0[BH * SDIM * DDIM];
__device__ float g_p1[BH * SDIM * DDIM];
__device__ float g_p2[BH * SDIM * DDIM];
__device__ float g_v [BH * SDIM * DDIM];
__device__ float g_s2[BH * DDIM];
__device__ float g_M [BH * DDIM * DDIM];
__device__ float g_t [BH * SDIM * DDIM];
__device__ float g_val[MTOT * EDIM];

// ---------------- big NT GEMM: C = X(M,K) @ W(N,K)^T + bias --------------
// MODE 0: write packed head layout p[(b*H+h)*S + s][d]   (proj kernels)
// MODE 1: write plain row-major C[m*N + n]               (output GEMM)
template <int MODE>
__global__ void __launch_bounds__(256) gemm_nt_kernel(
    const float* __restrict__ X, const float* __restrict__ W,
    const float* __restrict__ bias, float* __restrict__ Out)
{
    __shared__ float As[16][128];
    __shared__ float Bs[16][128];

    const int tid = threadIdx.x;
    const int tx = tid & 15, ty = tid >> 4;
    const int m0 = blockIdx.y * 128;
    const int n0 = blockIdx.x * 128;

    float acc[8][8];
#pragma unroll
    for (int i = 0; i < 8; i++)
#pragma unroll
        for (int j = 0; j < 8; j++) acc[i][j] = 0.f;

    for (int k0 = 0; k0 < EDIM; k0 += 16) {
#pragma unroll
        for (int l = 0; l < 2; l++) {
            int idx = tid + l * 256;           // 0..511
            int row = idx >> 2, kq = idx & 3;  // row 0..127, kq 0..3
            float4 a = *(const float4*)&X[(size_t)(m0 + row) * EDIM + k0 + kq * 4];
            As[kq * 4 + 0][row] = a.x; As[kq * 4 + 1][row] = a.y;
            As[kq * 4 + 2][row] = a.z; As[kq * 4 + 3][row] = a.w;
            float4 b = *(const float4*)&W[(size_t)(n0 + row) * EDIM + k0 + kq * 4];
            Bs[kq * 4 + 0][row] = b.x; Bs[kq * 4 + 1][row] = b.y;
            Bs[kq * 4 + 2][row] = b.z; Bs[kq * 4 + 3][row] = b.w;
        }
        __syncthreads();
#pragma unroll
        for (int kk = 0; kk < 16; kk++) {
            float a[8], b[8];
#pragma unroll
            for (int i = 0; i < 8; i++) a[i] = As[kk][ty * 8 + i];
#pragma unroll
            for (int j = 0; j < 8; j++) b[j] = Bs[kk][tx * 8 + j];
#pragma unroll
            for (int i = 0; i < 8; i++)
#pragma unroll
                for (int j = 0; j < 8; j++) acc[i][j] += a[i] * b[j];
        }
        __syncthreads();
    }

#pragma unroll
    for (int i = 0; i < 8; i++) {
        int m = m0 + ty * 8 + i;
#pragma unroll
        for (int j = 0; j < 8; j++) {
            int n = n0 + tx * 8 + j;
            float val = acc[i][j] + bias[n];
            if (MODE == 0) {
                int bb = m >> 10, ss = m & 1023;
                int h = n >> 6, d = n & 63;
                Out[(((size_t)(bb * HDIM + h) * SDIM) + ss) * DDIM + d] = val;
            } else {
                Out[(size_t)m * EDIM + n] = val;
            }
        }
    }
}

// ---------------- s2[bh,d] = sum_s p2[bh,s,d] ----------------------------
__global__ void s2_kernel(const float* __restrict__ P2, float* __restrict__ s2)
{
    __shared__ float red[8][64];
    int bh = blockIdx.x;
    int tid = threadIdx.x;        // 512
    int d = tid & 63, c = tid >> 6;  // c 0..7
    const float* p = P2 + (size_t)bh * SDIM * DDIM + d;
    float acc = 0.f;
    for (int s = c * 128; s < (c + 1) * 128; s++) acc += p[(size_t)s * DDIM];
    red[c][d] = acc;
    __syncthreads();
    if (c == 0) {
        float t = 0.f;
#pragma unroll
        for (int i = 0; i < 8; i++) t += red[i][d];
        s2[bh * DDIM + d] = t;
    }
}

// ---------------- M[bh,a,c] = sum_d A[a,c,d]*s2[bh,d] --------------------
__global__ void m_kernel(const float* __restrict__ A, const float* __restrict__ s2,
                         float* __restrict__ Mm)
{
    int bh = blockIdx.y, a = blockIdx.x;
    int c = threadIdx.x;  // 64
    __shared__ float s2s[64];
    s2s[c] = s2[bh * DDIM + c];
    __syncthreads();
    const float* Ap = A + ((size_t)a * DDIM + c) * DDIM;
    float acc = 0.f;
#pragma unroll
    for (int d = 0; d < 64; d++) acc += Ap[d] * s2s[d];
    Mm[(size_t)bh * 4096 + a * DDIM + c] = acc;
}

// ---------------- t[bh,i,c] = sum_a p0[bh,i,a]*M[bh,a,c] -----------------
__global__ void __launch_bounds__(256) t_kernel(
    const float* __restrict__ P0, const float* __restrict__ Mm, float* __restrict__ T)
{
    int bh = blockIdx.y;
    int i0 = blockIdx.x * 64;
    __shared__ float Ms[64 * 64];
    __shared__ float Ps[64 * 64];
    int tid = threadIdx.x;  // 256
    const float* Mp = Mm + (size_t)bh * 4096;
    const float* Pp = P0 + ((size_t)bh * SDIM + i0) * DDIM;
#pragma unroll
    for (int l = 0; l < 4; l++) {
        int idx = tid + l * 256;  // float4 index, 1024 total
        ((float4*)Ms)[idx] = ((const float4*)Mp)[idx];
        ((float4*)Ps)[idx] = ((const float4*)Pp)[idx];
    }
    __syncthreads();
    int row = tid >> 2, cq = tid & 3;
    float acc[16];
#pragma unroll
    for (int j = 0; j < 16; j++) acc[j] = 0.f;
    for (int a = 0; a < 64; a++) {
        float pa = Ps[row * 64 + a];
#pragma unroll
        for (int j = 0; j < 16; j++) acc[j] += pa * Ms[a * 64 + cq * 16 + j];
    }
    float* Tp = T + ((size_t)bh * SDIM + i0) * DDIM;
#pragma unroll
    for (int j = 0; j < 16; j++) Tp[row * 64 + cq * 16 + j] = acc[j];
}

// ---------------- logits: per-bh NT GEMM, K=64, *1/8 ---------------------
__global__ void __launch_bounds__(256) logits_kernel(
    const float* __restrict__ T, const float* __restrict__ P1, float* __restrict__ attn)
{
    int bh = blockIdx.z;
    const float* Ap = T  + (size_t)bh * SDIM * DDIM;
    const float* Bp = P1 + (size_t)bh * SDIM * DDIM;
    __shared__ float As[16][128];
    __shared__ float Bs[16][128];
    const int tid = threadIdx.x;
    const int tx = tid & 15, ty = tid >> 4;
    const int m0 = blockIdx.y * 128;
    const int n0 = blockIdx.x * 128;

    float acc[8][8];
#pragma unroll
    for (int i = 0; i < 8; i++)
#pragma unroll
        for (int j = 0; j < 8; j++) acc[i][j] = 0.f;

    for (int k0 = 0; k0 < DDIM; k0 += 16) {
#pragma unroll
        for (int l = 0; l < 2; l++) {
            int idx = tid + l * 256;
            int row = idx >> 2, kq = idx & 3;
            float4 a = *(const float4*)&Ap[(size_t)(m0 + row) * DDIM + k0 + kq * 4];
            As[kq * 4 + 0][row] = a.x; As[kq * 4 + 1][row] = a.y;
            As[kq * 4 + 2][row] = a.z; As[kq * 4 + 3][row] = a.w;
            float4 b = *(const float4*)&Bp[(size_t)(n0 + row) * DDIM + k0 + kq * 4];
            Bs[kq * 4 + 0][row] = b.x; Bs[kq * 4 + 1][row] = b.y;
            Bs[kq * 4 + 2][row] = b.z; Bs[kq * 4 + 3][row] = b.w;
        }
        __syncthreads();
#pragma unroll
        for (int kk = 0; kk < 16; kk++) {
            float a[8], b[8];
#pragma unroll
            for (int i = 0; i < 8; i++) a[i] = As[kk][ty * 8 + i];
#pragma unroll
            for (int j = 0; j < 8; j++) b[j] = Bs[kk][tx * 8 + j];
#pragma unroll
            for (int i = 0; i < 8; i++)
#pragma unroll
                for (int j = 0; j < 8; j++) acc[i][j] += a[i] * b[j];
        }
        __syncthreads();
    }

    float* Op = attn + (size_t)bh * SDIM * SDIM;
#pragma unroll
    for (int i = 0; i < 8; i++) {
        int m = m0 + ty * 8 + i;
#pragma unroll
        for (int j = 0; j < 8; j++) {
            int n = n0 + tx * 8 + j;
            Op[(size_t)m * SDIM + n] = acc[i][j] * 0.125f;  // / sqrt(64)
        }
    }
}

// ---------------- row softmax in place (row length 1024) -----------------
__global__ void __launch_bounds__(256) softmax_kernel(float* __restrict__ attn)
{
    size_t row = blockIdx.x;
    float4* rp = (float4*)(attn + row * SDIM);
    int tid = threadIdx.x;  // 256, 1 float4 each
    __shared__ float red[8];
    __shared__ float bc;

    float4 v = rp[tid];
    float m = fmaxf(fmaxf(v.x, v.y), fmaxf(v.z, v.w));
#pragma unroll
    for (int o = 16; o > 0; o >>= 1) m = fmaxf(m, __shfl_xor_sync(0xffffffffu, m, o));
    if ((tid & 31) == 0) red[tid >> 5] = m;
    __syncthreads();
    if (tid == 0) {
        float mm = red[0];
#pragma unroll
        for (int i = 1; i < 8; i++) mm = fmaxf(mm, red[i]);
        bc = mm;
    }
    __syncthreads();
    float mm = bc;
    v.x = __expf(v.x - mm); v.y = __expf(v.y - mm);
    v.z = __expf(v.z - mm); v.w = __expf(v.w - mm);
    float s = v.x + v.y + v.z + v.w;
#pragma unroll
    for (int o = 16; o > 0; o >>= 1) s += __shfl_xor_sync(0xffffffffu, s, o);
    if ((tid & 31) == 0) red[tid >> 5] = s;
    __syncthreads();
    if (tid == 0) {
        float ss = 0.f;
#pragma unroll
        for (int i = 0; i < 8; i++) ss += red[i];
        bc = 1.0f / ss;
    }
    __syncthreads();
    float inv = bc;
    v.x *= inv; v.y *= inv; v.z *= inv; v.w *= inv;
    rp[tid] = v;
}

// ---------------- values = attn @ v (NN, N=64), per bh -------------------
__global__ void __launch_bounds__(256) av_kernel(
    const float* __restrict__ attn, const float* __restrict__ V, float* __restrict__ Vals)
{
    int bh = blockIdx.z;
    int bb = bh >> 4, h = bh & 15;
    const float* Ap = attn + (size_t)bh * SDIM * SDIM;
    const float* Vp = V + (size_t)bh * SDIM * DDIM;
    __shared__ float As[16][128];
    __shared__ float Vs[16][64];
    int tid = threadIdx.x;  // 256
    int tx = tid & 15, ty = tid >> 4;
    int m0 = blockIdx.y * 128;

    float acc[8][4];
#pragma unroll
    for (int i = 0; i < 8; i++)
#pragma unroll
        for (int j = 0; j < 4; j++) acc[i][j] = 0.f;

    for (int k0 = 0; k0 < SDIM; k0 += 16) {
#pragma unroll
        for (int l = 0; l < 2; l++) {
            int idx = tid + l * 256;
            int row = idx >> 2, kq = idx & 3;
            float4 a = *(const float4*)&Ap[(size_t)(m0 + row) * SDIM + k0 + kq * 4];
            As[kq * 4 + 0][row] = a.x; As[kq * 4 + 1][row] = a.y;
            As[kq * 4 + 2][row] = a.z; As[kq * 4 + 3][row] = a.w;
        }
        {
            int kk = tid >> 4, dq = tid & 15;
            float4 b = *(const float4*)&Vp[(size_t)(k0 + kk) * DDIM + dq * 4];
            *(float4*)&Vs[kk][dq * 4] = b;
        }
        __syncthreads();
#pragma unroll
        for (int kk = 0; kk < 16; kk++) {
            float4 b = *(float4*)&Vs[kk][tx * 4];
#pragma unroll
            for (int i = 0; i < 8; i++) {
                float a = As[kk][ty * 8 + i];
                acc[i][0] += a * b.x; acc[i][1] += a * b.y;
                acc[i][2] += a * b.z; acc[i][3] += a * b.w;
            }
        }
        __syncthreads();
    }

#pragma unroll
    for (int i = 0; i < 8; i++) {
        int m = m0 + ty * 8 + i;
#pragma unroll
        for (int j = 0; j < 4; j++)
            Vals[((size_t)bb * SDIM + m) * EDIM + h * DDIM + tx * 4 + j] = acc[i][j];
    }
}

// ---------------- launch ----------------------------------------------
extern "C" void kernel_launch(void* const* d_in, const int* in_sizes, int n_in,
                              void* d_out, int out_size)
{
    const float* x  = (const float*)d_in[0];
    const float* W0 = (const float*)d_in[1];
    const float* b0 = (const float*)d_in[2];
    const float* W1 = (const float*)d_in[3];
    const float* b1 = (const float*)d_in[4];
    const float* W2 = (const float*)d_in[5];
    const float* b2 = (const float*)d_in[6];
    const float* Wv = (const float*)d_in[7];
    const float* bv = (const float*)d_in[8];
    const float* Wo = (const float*)d_in[9];
    const float* bo = (const float*)d_in[10];
    const float* A  = (const float*)d_in[11];

    float* out  = (float*)d_out;                       // (B,S,E) = 4M floats
    float* attn = out + (size_t)MTOT * EDIM;           // (B,H,S,S) = 64M floats

    float *p0, *p1, *p2, *v, *s2, *Mm, *T, *Vals;
    cudaGetSymbolAddress((void**)&p0, g_p0);
    cudaGetSymbolAddress((void**)&p1, g_p1);
    cudaGetSymbolAddress((void**)&p2, g_p2);
    cudaGetSymbolAddress((void**)&v,  g_v);
    cudaGetSymbolAddress((void**)&s2, g_s2);
    cudaGetSymbolAddress((void**)&Mm, g_M);
    cudaGetSymbolAddress((void**)&T,  g_t);
    cudaGetSymbolAddress((void**)&Vals, g_val);

    dim3 gProj(EDIM / 128, MTOT / 128);  // (8, 32)
    gemm_nt_kernel<0><<<gProj, 256>>>(x, W0, b0, p0);
    gemm_nt_kernel<0><<<gProj, 256>>>(x, W1, b1, p1);
    gemm_nt_kernel<0><<<gProj, 256>>>(x, W2, b2, p2);
    gemm_nt_kernel<0><<<gProj, 256>>>(x, Wv, bv, v);

    s2_kernel<<<BH, 512>>>(p2, s2);
    m_kernel<<<dim3(64, BH), 64>>>(A, s2, Mm);
    t_kernel<<<dim3(16, BH), 256>>>(p0, Mm, T);

    logits_kernel<<<dim3(8, 8, BH), 256>>>(T, p1, attn);
    softmax_kernel<<<BH * SDIM, 256>>>(attn);
    av_kernel<<<dim3(1, 8, BH), 256>>>(attn, v, Vals);

    gemm_nt_kernel<1><<<gProj, 256>>>(Vals, Wo, bo, out);
}

// round 2
// speedup vs baseline: 1.6021x; 1.6021x over previous
#include <cuda_runtime.h>
#include <cuda_bf16.h>
#include <math.h>

#define SDIM 1024
#define EDIM 1024
#define BDIM 4
#define HDIM 16
#define DDIM 64
#define BH   64          // BDIM*HDIM
#define MTOT 4096        // BDIM*SDIM

// ---------------- scratch (device globals; no allocation) ----------------
__device__ float g_p0[BH * SDIM * DDIM];
__device__ float g_p1[BH * SDIM * DDIM];
__device__ float g_p2[BH * SDIM * DDIM];
__device__ float g_v [BH * SDIM * DDIM];
__device__ float g_s2[BH * DDIM];
__device__ float g_M [BH * DDIM * DDIM];
__device__ float g_t [BH * SDIM * DDIM];
__device__ float g_val[MTOT * EDIM];

// ---------------- helpers -------------------------------------------------
__device__ __forceinline__ unsigned s2u(const void* p) {
    return (unsigned)__cvta_generic_to_shared(p);
}
__device__ __forceinline__ void ldsm4(unsigned* r, unsigned addr) {
    asm volatile("ldmatrix.sync.aligned.m8n8.x4.shared.b16 {%0,%1,%2,%3}, [%4];"
                 : "=r"(r[0]), "=r"(r[1]), "=r"(r[2]), "=r"(r[3]) : "r"(addr));
}
__device__ __forceinline__ void mma16816(float* c, const unsigned* a, const unsigned* b) {
    asm volatile("mma.sync.aligned.m16n8k16.row.col.f32.bf16.bf16.f32 "
                 "{%0,%1,%2,%3}, {%4,%5,%6,%7}, {%8,%9}, {%0,%1,%2,%3};"
                 : "+f"(c[0]), "+f"(c[1]), "+f"(c[2]), "+f"(c[3])
                 : "r"(a[0]), "r"(a[1]), "r"(a[2]), "r"(a[3]), "r"(b[0]), "r"(b[1]));
}

// ---------------- tensor-core NT GEMM with bf16 split-3 -------------------
// C = X(M,1024) @ W(N,1024)^T + bias ; 128x128 tile, 8 warps of 64x32.
// MODE 0: packed head layout  p[(b*H+h)*S + s][d]
// MODE 1: row-major           C[m*1024 + n]
#define KT    32       // K-tile
#define LDSS  40       // smem row stride in bf16 elems (80 bytes, conflict-free)

template <int MODE>
__global__ void __launch_bounds__(256, 1) gemm_tc_kernel(
    const float* __restrict__ X, const float* __restrict__ W,
    const float* __restrict__ bias, float* __restrict__ Out)
{
    __shared__ __nv_bfloat16 Ah[128 * LDSS];
    __shared__ __nv_bfloat16 Al[128 * LDSS];
    __shared__ __nv_bfloat16 Bh[128 * LDSS];
    __shared__ __nv_bfloat16 Bl[128 * LDSS];

    const int tid  = threadIdx.x;
    const int lane = tid & 31;
    const int wid  = tid >> 5;
    const int m0 = blockIdx.y * 128;
    const int n0 = blockIdx.x * 128;
    const int wm = (wid >> 2) * 64;   // 2 warps in m
    const int wn = (wid & 3) * 32;    // 4 warps in n

    // prefetch registers
    float4 pa[4], pb[4];

    // ldmatrix base addresses (bytes)
    unsigned baA[4], baAl[4], baB[2], baBl[2];
    {
        int ar = lane & 15, ak = (lane >> 4) * 8;
#pragma unroll
        for (int mi = 0; mi < 4; mi++) {
            int off = ((wm + mi * 16 + ar) * LDSS + ak) * 2;
            baA[mi]  = s2u(Ah) + off;
            baAl[mi] = s2u(Al) + off;
        }
        int nr = (lane & 7) + ((lane >> 4) & 1) * 8;
        int nk = ((lane >> 3) & 1) * 8;
#pragma unroll
        for (int np = 0; np < 2; np++) {
            int off = ((wn + np * 16 + nr) * LDSS + nk) * 2;
            baB[np]  = s2u(Bh) + off;
            baBl[np] = s2u(Bl) + off;
        }
    }

    float acc[4][4][4];
#pragma unroll
    for (int i = 0; i < 4; i++)
#pragma unroll
        for (int j = 0; j < 4; j++)
#pragma unroll
            for (int e = 0; e < 4; e++) acc[i][j][e] = 0.f;

    auto loadTile = [&](int k0) {
#pragma unroll
        for (int l = 0; l < 4; l++) {
            int idx = l * 256 + tid;
            int row = idx >> 3, kq = (idx & 7) * 4;
            pa[l] = *(const float4*)&X[(size_t)(m0 + row) * EDIM + k0 + kq];
            pb[l] = *(const float4*)&W[(size_t)(n0 + row) * EDIM + k0 + kq];
        }
    };
    auto storeTile = [&]() {
#pragma unroll
        for (int l = 0; l < 4; l++) {
            int idx = l * 256 + tid;
            int row = idx >> 3, kq = (idx & 7) * 4;
            int o = row * LDSS + kq;
            float4 a = pa[l];
            __nv_bfloat16 hx = __float2bfloat16_rn(a.x);
            __nv_bfloat16 hy = __float2bfloat16_rn(a.y);
            __nv_bfloat16 hz = __float2bfloat16_rn(a.z);
            __nv_bfloat16 hw = __float2bfloat16_rn(a.w);
            *(__nv_bfloat162*)&Ah[o]     = __nv_bfloat162(hx, hy);
            *(__nv_bfloat162*)&Ah[o + 2] = __nv_bfloat162(hz, hw);
            *(__nv_bfloat162*)&Al[o]     = __nv_bfloat162(
                __float2bfloat16_rn(a.x - __bfloat162float(hx)),
                __float2bfloat16_rn(a.y - __bfloat162float(hy)));
            *(__nv_bfloat162*)&Al[o + 2] = __nv_bfloat162(
                __float2bfloat16_rn(a.z - __bfloat162float(hz)),
                __float2bfloat16_rn(a.w - __bfloat162float(hw)));
            float4 b = pb[l];
            hx = __float2bfloat16_rn(b.x); hy = __float2bfloat16_rn(b.y);
            hz = __float2bfloat16_rn(b.z); hw = __float2bfloat16_rn(b.w);
            *(__nv_bfloat162*)&Bh[o]     = __nv_bfloat162(hx, hy);
            *(__nv_bfloat162*)&Bh[o + 2] = __nv_bfloat162(hz, hw);
            *(__nv_bfloat162*)&Bl[o]     = __nv_bfloat162(
                __float2bfloat16_rn(b.x - __bfloat162float(hx)),
                __float2bfloat16_rn(b.y - __bfloat162float(hy)));
            *(__nv_bfloat162*)&Bl[o + 2] = __nv_bfloat162(
                __float2bfloat16_rn(b.z - __bfloat162float(hz)),
                __float2bfloat16_rn(b.w - __bfloat162float(hw)));
        }
    };

    loadTile(0);
    storeTile();
    __syncthreads();

    for (int kt = 0; kt < EDIM / KT; kt++) {
        bool has_next = (kt + 1) < EDIM / KT;
        if (has_next) loadTile((kt + 1) * KT);

#pragma unroll
        for (int kk = 0; kk < 2; kk++) {   // two k16 steps per K-tile
            unsigned boff = kk * 32;       // 16 bf16 = 32 bytes
            unsigned ah[4][4], al[4][4], bh[4][2], bl[4][2];
#pragma unroll
            for (int mi = 0; mi < 4; mi++) ldsm4(ah[mi], baA[mi] + boff);
#pragma unroll
            for (int np = 0; np < 2; np++) {
                unsigned r[4];
                ldsm4(r, baB[np] + boff);
                bh[2 * np][0] = r[0]; bh[2 * np][1] = r[1];
                bh[2 * np + 1][0] = r[2]; bh[2 * np + 1][1] = r[3];
            }
#pragma unroll
            for (int mi = 0; mi < 4; mi++)
#pragma unroll
                for (int ni = 0; ni < 4; ni++) mma16816(acc[mi][ni], ah[mi], bh[ni]);

#pragma unroll
            for (int np = 0; np < 2; np++) {
                unsigned r[4];
                ldsm4(r, baBl[np] + boff);
                bl[2 * np][0] = r[0]; bl[2 * np][1] = r[1];
                bl[2 * np + 1][0] = r[2]; bl[2 * np + 1][1] = r[3];
            }
#pragma unroll
            for (int mi = 0; mi < 4; mi++)
#pragma unroll
                for (int ni = 0; ni < 4; ni++) mma16816(acc[mi][ni], ah[mi], bl[ni]);

#pragma unroll
            for (int mi = 0; mi < 4; mi++) ldsm4(al[mi], baAl[mi] + boff);
#pragma unroll
            for (int mi = 0; mi < 4; mi++)
#pragma unroll
                for (int ni = 0; ni < 4; ni++) mma16816(acc[mi][ni], al[mi], bh[ni]);
        }

        __syncthreads();
        if (has_next) {
            storeTile();
            __syncthreads();
        }
    }

    // epilogue
    const int g = lane >> 2;
    const int cq = (lane & 3) * 2;
#pragma unroll
    for (int mi = 0; mi < 4; mi++) {
#pragma unroll
        for (int ni = 0; ni < 4; ni++) {
            int col = n0 + wn + ni * 8 + cq;
            float2 bia = *(const float2*)&bias[col];
#pragma unroll
            for (int half = 0; half < 2; half++) {
                int row = m0 + wm + mi * 16 + g + half * 8;
                float v0 = acc[mi][ni][half * 2 + 0] + bia.x;
                float v1 = acc[mi][ni][half * 2 + 1] + bia.y;
                if (MODE == 0) {
                    int bb = row >> 10, ss = row & 1023;
                    int h = col >> 6, d = col & 63;
                    float2* dst = (float2*)&Out[(((size_t)(bb * HDIM + h) * SDIM) + ss) * DDIM + d];
                    *dst = make_float2(v0, v1);
                } else {
                    *(float2*)&Out[(size_t)row * EDIM + col] = make_float2(v0, v1);
                }
            }
        }
    }
}

// ---------------- s2[bh,d] = sum_s p2[bh,s,d] ----------------------------
__global__ void s2_kernel(const float* __restrict__ P2, float* __restrict__ s2)
{
    __shared__ float red[8][64];
    int bh = blockIdx.x;
    int tid = threadIdx.x;        // 512
    int d = tid & 63, c = tid >> 6;  // c 0..7
    const float* p = P2 + (size_t)bh * SDIM * DDIM + d;
    float acc = 0.f;
    for (int s = c * 128; s < (c + 1) * 128; s++) acc += p[(size_t)s * DDIM];
    red[c][d] = acc;
    __syncthreads();
    if (c == 0) {
        float t = 0.f;
#pragma unroll
        for (int i = 0; i < 8; i++) t += red[i][d];
        s2[bh * DDIM + d] = t;
    }
}

// ---------------- M[bh,a,c] = sum_d A[a,c,d]*s2[bh,d] --------------------
__global__ void m_kernel(const float* __restrict__ A, const float* __restrict__ s2,
                         float* __restrict__ Mm)
{
    int bh = blockIdx.y, a = blockIdx.x;
    int c = threadIdx.x;  // 64
    __shared__ float s2s[64];
    s2s[c] = s2[bh * DDIM + c];
    __syncthreads();
    const float* Ap = A + ((size_t)a * DDIM + c) * DDIM;
    float acc = 0.f;
#pragma unroll
    for (int d = 0; d < 64; d++) acc += Ap[d] * s2s[d];
    Mm[(size_t)bh * 4096 + a * DDIM + c] = acc;
}

// ---------------- t[bh,i,c] = sum_a p0[bh,i,a]*M[bh,a,c] -----------------
__global__ void __launch_bounds__(256) t_kernel(
    const float* __restrict__ P0, const float* __restrict__ Mm, float* __restrict__ T)
{
    int bh = blockIdx.y;
    int i0 = blockIdx.x * 64;
    __shared__ float Ms[64 * 64];
    __shared__ float Ps[64 * 64];
    int tid = threadIdx.x;  // 256
    const float* Mp = Mm + (size_t)bh * 4096;
    const float* Pp = P0 + ((size_t)bh * SDIM + i0) * DDIM;
#pragma unroll
    for (int l = 0; l < 4; l++) {
        int idx = tid + l * 256;
        ((float4*)Ms)[idx] = ((const float4*)Mp)[idx];
        ((float4*)Ps)[idx] = ((const float4*)Pp)[idx];
    }
    __syncthreads();
    int row = tid >> 2, cq = tid & 3;
    float acc[16];
#pragma unroll
    for (int j = 0; j < 16; j++) acc[j] = 0.f;
    for (int a = 0; a < 64; a++) {
        float pa = Ps[row * 64 + a];
#pragma unroll
        for (int j = 0; j < 16; j++) acc[j] += pa * Ms[a * 64 + cq * 16 + j];
    }
    float* Tp = T + ((size_t)bh * SDIM + i0) * DDIM;
#pragma unroll
    for (int j = 0; j < 16; j++) Tp[row * 64 + cq * 16 + j] = acc[j];
}

// ---------------- logits: per-bh NT GEMM, K=64, *1/8 ---------------------
__global__ void __launch_bounds__(256) logits_kernel(
    const float* __restrict__ T, const float* __restrict__ P1, float* __restrict__ attn)
{
    int bh = blockIdx.z;
    const float* Ap = T  + (size_t)bh * SDIM * DDIM;
    const float* Bp = P1 + (size_t)bh * SDIM * DDIM;
    __shared__ float As[16][128];
    __shared__ float Bs[16][128];
    const int tid = threadIdx.x;
    const int tx = tid & 15, ty = tid >> 4;
    const int m0 = blockIdx.y * 128;
    const int n0 = blockIdx.x * 128;

    float acc[8][8];
#pragma unroll
    for (int i = 0; i < 8; i++)
#pragma unroll
        for (int j = 0; j < 8; j++) acc[i][j] = 0.f;

    for (int k0 = 0; k0 < DDIM; k0 += 16) {
#pragma unroll
        for (int l = 0; l < 2; l++) {
            int idx = tid + l * 256;
            int row = idx >> 2, kq = idx & 3;
            float4 a = *(const float4*)&Ap[(size_t)(m0 + row) * DDIM + k0 + kq * 4];
            As[kq * 4 + 0][row] = a.x; As[kq * 4 + 1][row] = a.y;
            As[kq * 4 + 2][row] = a.z; As[kq * 4 + 3][row] = a.w;
            float4 b = *(const float4*)&Bp[(size_t)(n0 + row) * DDIM + k0 + kq * 4];
            Bs[kq * 4 + 0][row] = b.x; Bs[kq * 4 + 1][row] = b.y;
            Bs[kq * 4 + 2][row] = b.z; Bs[kq * 4 + 3][row] = b.w;
        }
        __syncthreads();
#pragma unroll
        for (int kk = 0; kk < 16; kk++) {
            float a[8], b[8];
#pragma unroll
            for (int i = 0; i < 8; i++) a[i] = As[kk][ty * 8 + i];
#pragma unroll
            for (int j = 0; j < 8; j++) b[j] = Bs[kk][tx * 8 + j];
#pragma unroll
            for (int i = 0; i < 8; i++)
#pragma unroll
                for (int j = 0; j < 8; j++) acc[i][j] += a[i] * b[j];
        }
        __syncthreads();
    }

    float* Op = attn + (size_t)bh * SDIM * SDIM;
#pragma unroll
    for (int i = 0; i < 8; i++) {
        int m = m0 + ty * 8 + i;
#pragma unroll
        for (int j = 0; j < 8; j++) {
            int n = n0 + tx * 8 + j;
            Op[(size_t)m * SDIM + n] = acc[i][j] * 0.125f;  // / sqrt(64)
        }
    }
}

// ---------------- row softmax in place (row length 1024) -----------------
__global__ void __launch_bounds__(256) softmax_kernel(float* __restrict__ attn)
{
    size_t row = blockIdx.x;
    float4* rp = (float4*)(attn + row * SDIM);
    int tid = threadIdx.x;  // 256, 1 float4 each
    __shared__ float red[8];
    __shared__ float bc;

    float4 v = rp[tid];
    float m = fmaxf(fmaxf(v.x, v.y), fmaxf(v.z, v.w));
#pragma unroll
    for (int o = 16; o > 0; o >>= 1) m = fmaxf(m, __shfl_xor_sync(0xffffffffu, m, o));
    if ((tid & 31) == 0) red[tid >> 5] = m;
    __syncthreads();
    if (tid == 0) {
        float mm = red[0];
#pragma unroll
        for (int i = 1; i < 8; i++) mm = fmaxf(mm, red[i]);
        bc = mm;
    }
    __syncthreads();
    float mm = bc;
    v.x = __expf(v.x - mm); v.y = __expf(v.y - mm);
    v.z = __expf(v.z - mm); v.w = __expf(v.w - mm);
    float s = v.x + v.y + v.z + v.w;
#pragma unroll
    for (int o = 16; o > 0; o >>= 1) s += __shfl_xor_sync(0xffffffffu, s, o);
    if ((tid & 31) == 0) red[tid >> 5] = s;
    __syncthreads();
    if (tid == 0) {
        float ss = 0.f;
#pragma unroll
        for (int i = 0; i < 8; i++) ss += red[i];
        bc = 1.0f / ss;
    }
    __syncthreads();
    float inv = bc;
    v.x *= inv; v.y *= inv; v.z *= inv; v.w *= inv;
    rp[tid] = v;
}

// ---------------- values = attn @ v (NN, N=64), per bh -------------------
__global__ void __launch_bounds__(256) av_kernel(
    const float* __restrict__ attn, const float* __restrict__ V, float* __restrict__ Vals)
{
    int bh = blockIdx.z;
    int bb = bh >> 4, h = bh & 15;
    const float* Ap = attn + (size_t)bh * SDIM * SDIM;
    const float* Vp = V + (size_t)bh * SDIM * DDIM;
    __shared__ float As[16][128];
    __shared__ float Vs[16][64];
    int tid = threadIdx.x;  // 256
    int tx = tid & 15, ty = tid >> 4;
    int m0 = blockIdx.y * 128;

    float acc[8][4];
#pragma unroll
    for (int i = 0; i < 8; i++)
#pragma unroll
        for (int j = 0; j < 4; j++) acc[i][j] = 0.f;

    for (int k0 = 0; k0 < SDIM; k0 += 16) {
#pragma unroll
        for (int l = 0; l < 2; l++) {
            int idx = tid + l * 256;
            int row = idx >> 2, kq = idx & 3;
            float4 a = *(const float4*)&Ap[(size_t)(m0 + row) * SDIM + k0 + kq * 4];
            As[kq * 4 + 0][row] = a.x; As[kq * 4 + 1][row] = a.y;
            As[kq * 4 + 2][row] = a.z; As[kq * 4 + 3][row] = a.w;
        }
        {
            int kk = tid >> 4, dq = tid & 15;
            float4 b = *(const float4*)&Vp[(size_t)(k0 + kk) * DDIM + dq * 4];
            *(float4*)&Vs[kk][dq * 4] = b;
        }
        __syncthreads();
#pragma unroll
        for (int kk = 0; kk < 16; kk++) {
            float4 b = *(float4*)&Vs[kk][tx * 4];
#pragma unroll
            for (int i = 0; i < 8; i++) {
                float a = As[kk][ty * 8 + i];
                acc[i][0] += a * b.x; acc[i][1] += a * b.y;
                acc[i][2] += a * b.z; acc[i][3] += a * b.w;
            }
        }
        __syncthreads();
    }

#pragma unroll
    for (int i = 0; i < 8; i++) {
        int m = m0 + ty * 8 + i;
#pragma unroll
        for (int j = 0; j < 4; j++)
            Vals[((size_t)bb * SDIM + m) * EDIM + h * DDIM + tx * 4 + j] = acc[i][j];
    }
}

// ---------------- launch ----------------------------------------------
extern "C" void kernel_launch(void* const* d_in, const int* in_sizes, int n_in,
                              void* d_out, int out_size)
{
    const float* x  = (const float*)d_in[0];
    const float* W0 = (const float*)d_in[1];
    const float* b0 = (const float*)d_in[2];
    const float* W1 = (const float*)d_in[3];
    const float* b1 = (const float*)d_in[4];
    const float* W2 = (const float*)d_in[5];
    const float* b2 = (const float*)d_in[6];
    const float* Wv = (const float*)d_in[7];
    const float* bv = (const float*)d_in[8];
    const float* Wo = (const float*)d_in[9];
    const float* bo = (const float*)d_in[10];
    const float* A  = (const float*)d_in[11];

    float* out  = (float*)d_out;                       // (B,S,E) = 4M floats
    float* attn = out + (size_t)MTOT * EDIM;           // (B,H,S,S) = 64M floats

    float *p0, *p1, *p2, *v, *s2, *Mm, *T, *Vals;
    cudaGetSymbolAddress((void**)&p0, g_p0);
    cudaGetSymbolAddress((void**)&p1, g_p1);
    cudaGetSymbolAddress((void**)&p2, g_p2);
    cudaGetSymbolAddress((void**)&v,  g_v);
    cudaGetSymbolAddress((void**)&s2, g_s2);
    cudaGetSymbolAddress((void**)&Mm, g_M);
    cudaGetSymbolAddress((void**)&T,  g_t);
    cudaGetSymbolAddress((void**)&Vals, g_val);

    dim3 gProj(EDIM / 128, MTOT / 128);  // (8, 32)
    gemm_tc_kernel<0><<<gProj, 256>>>(x, W0, b0, p0);
    gemm_tc_kernel<0><<<gProj, 256>>>(x, W1, b1, p1);
    gemm_tc_kernel<0><<<gProj, 256>>>(x, W2, b2, p2);
    gemm_tc_kernel<0><<<gProj, 256>>>(x, Wv, bv, v);

    s2_kernel<<<BH, 512>>>(p2, s2);
    m_kernel<<<dim3(64, BH), 64>>>(A, s2, Mm);
    t_kernel<<<dim3(16, BH), 256>>>(p0, Mm, T);

    logits_kernel<<<dim3(8, 8, BH), 256>>>(T, p1, attn);
    softmax_kernel<<<BH * SDIM, 256>>>(attn);
    av_kernel<<<dim3(1, 8, BH), 256>>>(attn, v, Vals);

    gemm_tc_kernel<1><<<gProj, 256>>>(Vals, Wo, bo, out);
}

// round 4
// speedup vs baseline: 1.9097x; 1.1920x over previous
#include <cuda_runtime.h>
#include <cuda_bf16.h>
#include <math.h>

#define SDIM 1024
#define EDIM 1024
#define BDIM 4
#define HDIM 16
#define DDIM 64
#define BH   64
#define MTOT 4096

// ---------------- scratch (device globals; no allocation) ----------------
__device__ float g_p0[BH * SDIM * DDIM];
__device__ float g_p1[BH * SDIM * DDIM];
__device__ float g_p2[BH * SDIM * DDIM];
__device__ float g_v [BH * SDIM * DDIM];
__device__ float g_s2[BH * DDIM];
__device__ float g_M [BH * DDIM * DDIM];
__device__ float g_t [BH * SDIM * DDIM];
__device__ float g_val[MTOT * EDIM];
__device__ __nv_bfloat16 g_vth[BH * DDIM * SDIM];
__device__ __nv_bfloat16 g_vtl[BH * DDIM * SDIM];

// ---------------- helpers -------------------------------------------------
__device__ __forceinline__ unsigned s2u(const void* p) {
    return (unsigned)__cvta_generic_to_shared(p);
}
__device__ __forceinline__ void ldsm4(unsigned* r, unsigned addr) {
    asm volatile("ldmatrix.sync.aligned.m8n8.x4.shared.b16 {%0,%1,%2,%3}, [%4];"
                 : "=r"(r[0]), "=r"(r[1]), "=r"(r[2]), "=r"(r[3]) : "r"(addr));
}
__device__ __forceinline__ void mma16816(float* c, const unsigned* a, const unsigned* b) {
    asm volatile("mma.sync.aligned.m16n8k16.row.col.f32.bf16.bf16.f32 "
                 "{%0,%1,%2,%3}, {%4,%5,%6,%7}, {%8,%9}, {%0,%1,%2,%3};"
                 : "+f"(c[0]), "+f"(c[1]), "+f"(c[2]), "+f"(c[3])
                 : "r"(a[0]), "r"(a[1]), "r"(a[2]), "r"(a[3]), "r"(b[0]), "r"(b[1]));
}
__device__ __forceinline__ void mma_tf32(float* c, const unsigned* a, unsigned b0, unsigned b1) {
    asm volatile("mma.sync.aligned.m16n8k8.row.col.f32.tf32.tf32.f32 "
                 "{%0,%1,%2,%3}, {%4,%5,%6,%7}, {%8,%9}, {%0,%1,%2,%3};"
                 : "+f"(c[0]), "+f"(c[1]), "+f"(c[2]), "+f"(c[3])
                 : "r"(a[0]), "r"(a[1]), "r"(a[2]), "r"(a[3]), "r"(b0), "r"(b1));
}
__device__ __forceinline__ unsigned f2tf(float x) {
    unsigned r;
    asm("cvt.rna.tf32.f32 %0, %1;" : "=r"(r) : "f"(x));
    return r;
}

// ---------------- tensor-core NT GEMM core (bf16 split-3) -----------------
#define KT    32
#define LDSS  40

template <int MODE>
__device__ __forceinline__ void gemm_core(
    const float* __restrict__ X, const float* __restrict__ W,
    const float* __restrict__ bias, float* __restrict__ Out)
{
    __shared__ __nv_bfloat16 Ah[128 * LDSS];
    __shared__ __nv_bfloat16 Al[128 * LDSS];
    __shared__ __nv_bfloat16 Bh[128 * LDSS];
    __shared__ __nv_bfloat16 Bl[128 * LDSS];

    const int tid  = threadIdx.x;
    const int lane = tid & 31;
    const int wid  = tid >> 5;
    const int m0 = blockIdx.y * 128;
    const int n0 = blockIdx.x * 128;
    const int wm = (wid >> 2) * 64;
    const int wn = (wid & 3) * 32;

    float4 pa[4], pb[4];

    unsigned baA[4], baAl[4], baB[2], baBl[2];
    {
        int ar = lane & 15, ak = (lane >> 4) * 8;
#pragma unroll
        for (int mi = 0; mi < 4; mi++) {
            int off = ((wm + mi * 16 + ar) * LDSS + ak) * 2;
            baA[mi]  = s2u(Ah) + off;
            baAl[mi] = s2u(Al) + off;
        }
        int nr = (lane & 7) + ((lane >> 4) & 1) * 8;
        int nk = ((lane >> 3) & 1) * 8;
#pragma unroll
        for (int np = 0; np < 2; np++) {
            int off = ((wn + np * 16 + nr) * LDSS + nk) * 2;
            baB[np]  = s2u(Bh) + off;
            baBl[np] = s2u(Bl) + off;
        }
    }

    float acc[4][4][4];
#pragma unroll
    for (int i = 0; i < 4; i++)
#pragma unroll
        for (int j = 0; j < 4; j++)
#pragma unroll
            for (int e = 0; e < 4; e++) acc[i][j][e] = 0.f;

    auto loadTile = [&](int k0) {
#pragma unroll
        for (int l = 0; l < 4; l++) {
            int idx = l * 256 + tid;
            int row = idx >> 3, kq = (idx & 7) * 4;
            pa[l] = *(const float4*)&X[(size_t)(m0 + row) * EDIM + k0 + kq];
            pb[l] = *(const float4*)&W[(size_t)(n0 + row) * EDIM + k0 + kq];
        }
    };
    auto storeTile = [&]() {
#pragma unroll
        for (int l = 0; l < 4; l++) {
            int idx = l * 256 + tid;
            int row = idx >> 3, kq = (idx & 7) * 4;
            int o = row * LDSS + kq;
            float4 a = pa[l];
            __nv_bfloat16 hx = __float2bfloat16_rn(a.x);
            __nv_bfloat16 hy = __float2bfloat16_rn(a.y);
            __nv_bfloat16 hz = __float2bfloat16_rn(a.z);
            __nv_bfloat16 hw = __float2bfloat16_rn(a.w);
            *(__nv_bfloat162*)&Ah[o]     = __nv_bfloat162(hx, hy);
            *(__nv_bfloat162*)&Ah[o + 2] = __nv_bfloat162(hz, hw);
            *(__nv_bfloat162*)&Al[o]     = __nv_bfloat162(
                __float2bfloat16_rn(a.x - __bfloat162float(hx)),
                __float2bfloat16_rn(a.y - __bfloat162float(hy)));
            *(__nv_bfloat162*)&Al[o + 2] = __nv_bfloat162(
                __float2bfloat16_rn(a.z - __bfloat162float(hz)),
                __float2bfloat16_rn(a.w - __bfloat162float(hw)));
            float4 b = pb[l];
            hx = __float2bfloat16_rn(b.x); hy = __float2bfloat16_rn(b.y);
            hz = __float2bfloat16_rn(b.z); hw = __float2bfloat16_rn(b.w);
            *(__nv_bfloat162*)&Bh[o]     = __nv_bfloat162(hx, hy);
            *(__nv_bfloat162*)&Bh[o + 2] = __nv_bfloat162(hz, hw);
            *(__nv_bfloat162*)&Bl[o]     = __nv_bfloat162(
                __float2bfloat16_rn(b.x - __bfloat162float(hx)),
                __float2bfloat16_rn(b.y - __bfloat162float(hy)));
            *(__nv_bfloat162*)&Bl[o + 2] = __nv_bfloat162(
                __float2bfloat16_rn(b.z - __bfloat162float(hz)),
                __float2bfloat16_rn(b.w - __bfloat162float(hw)));
        }
    };

    loadTile(0);
    storeTile();
    __syncthreads();

    for (int kt = 0; kt < EDIM / KT; kt++) {
        bool has_next = (kt + 1) < EDIM / KT;
        if (has_next) loadTile((kt + 1) * KT);

#pragma unroll
        for (int kk = 0; kk < 2; kk++) {
            unsigned boff = kk * 32;
            unsigned ah[4][4], al[4][4], bh[4][2], bl[4][2];
#pragma unroll
            for (int mi = 0; mi < 4; mi++) ldsm4(ah[mi], baA[mi] + boff);
#pragma unroll
            for (int np = 0; np < 2; np++) {
                unsigned r[4];
                ldsm4(r, baB[np] + boff);
                bh[2 * np][0] = r[0]; bh[2 * np][1] = r[1];
                bh[2 * np + 1][0] = r[2]; bh[2 * np + 1][1] = r[3];
            }
#pragma unroll
            for (int mi = 0; mi < 4; mi++)
#pragma unroll
                for (int ni = 0; ni < 4; ni++) mma16816(acc[mi][ni], ah[mi], bh[ni]);

#pragma unroll
            for (int np = 0; np < 2; np++) {
                unsigned r[4];
                ldsm4(r, baBl[np] + boff);
                bl[2 * np][0] = r[0]; bl[2 * np][1] = r[1];
                bl[2 * np + 1][0] = r[2]; bl[2 * np + 1][1] = r[3];
            }
#pragma unroll
            for (int mi = 0; mi < 4; mi++)
#pragma unroll
                for (int ni = 0; ni < 4; ni++) mma16816(acc[mi][ni], ah[mi], bl[ni]);

#pragma unroll
            for (int mi = 0; mi < 4; mi++) ldsm4(al[mi], baAl[mi] + boff);
#pragma unroll
            for (int mi = 0; mi < 4; mi++)
#pragma unroll
                for (int ni = 0; ni < 4; ni++) mma16816(acc[mi][ni], al[mi], bh[ni]);
        }

        __syncthreads();
        if (has_next) {
            storeTile();
            __syncthreads();
        }
    }

    const int g = lane >> 2;
    const int cq = (lane & 3) * 2;
#pragma unroll
    for (int mi = 0; mi < 4; mi++) {
#pragma unroll
        for (int ni = 0; ni < 4; ni++) {
            int col = n0 + wn + ni * 8 + cq;
            float2 bia = *(const float2*)&bias[col];
#pragma unroll
            for (int half = 0; half < 2; half++) {
                int row = m0 + wm + mi * 16 + g + half * 8;
                float v0 = acc[mi][ni][half * 2 + 0] + bia.x;
                float v1 = acc[mi][ni][half * 2 + 1] + bia.y;
                if (MODE == 0) {
                    int bb = row >> 10, ss = row & 1023;
                    int h = col >> 6, d = col & 63;
                    *(float2*)&Out[(((size_t)(bb * HDIM + h) * SDIM) + ss) * DDIM + d]
                        = make_float2(v0, v1);
                } else {
                    *(float2*)&Out[(size_t)row * EDIM + col] = make_float2(v0, v1);
                }
            }
        }
    }
}

__global__ void __launch_bounds__(256, 1) gemm_proj_kernel(
    const float* __restrict__ X,
    const float* __restrict__ Wa, const float* __restrict__ ba, float* __restrict__ oa,
    const float* __restrict__ Wb, const float* __restrict__ bb, float* __restrict__ ob,
    const float* __restrict__ Wc, const float* __restrict__ bc, float* __restrict__ oc,
    const float* __restrict__ Wd, const float* __restrict__ bd, float* __restrict__ od)
{
    switch (blockIdx.z) {
        case 0: gemm_core<0>(X, Wa, ba, oa); break;
        case 1: gemm_core<0>(X, Wb, bb, ob); break;
        case 2: gemm_core<0>(X, Wc, bc, oc); break;
        default: gemm_core<0>(X, Wd, bd, od); break;
    }
}

__global__ void __launch_bounds__(256, 1) gemm_out_kernel(
    const float* __restrict__ X, const float* __restrict__ W,
    const float* __restrict__ bias, float* __restrict__ Out)
{
    gemm_core<1>(X, W, bias, Out);
}

// ---------------- s2[bh,d] = sum_s p2[bh,s,d] ----------------------------
__global__ void s2_kernel(const float* __restrict__ P2, float* __restrict__ s2)
{
    __shared__ float red[8][64];
    int bh = blockIdx.x;
    int tid = threadIdx.x;
    int d = tid & 63, c = tid >> 6;
    const float* p = P2 + (size_t)bh * SDIM * DDIM + d;
    float acc = 0.f;
    for (int s = c * 128; s < (c + 1) * 128; s++) acc += p[(size_t)s * DDIM];
    red[c][d] = acc;
    __syncthreads();
    if (c == 0) {
        float t = 0.f;
#pragma unroll
        for (int i = 0; i < 8; i++) t += red[i][d];
        s2[bh * DDIM + d] = t;
    }
}

// ---------------- M[bh,a,c] = sum_d A[a,c,d]*s2[bh,d] --------------------
__global__ void m_kernel(const float* __restrict__ A, const float* __restrict__ s2,
                         float* __restrict__ Mm)
{
    int bh = blockIdx.y, a = blockIdx.x;
    int c = threadIdx.x;
    __shared__ float s2s[64];
    s2s[c] = s2[bh * DDIM + c];
    __syncthreads();
    const float* Ap = A + ((size_t)a * DDIM + c) * DDIM;
    float acc = 0.f;
#pragma unroll
    for (int d = 0; d < 64; d++) acc += Ap[d] * s2s[d];
    Mm[(size_t)bh * 4096 + a * DDIM + c] = acc;
}

// ---------------- t[bh,i,c] = sum_a p0[bh,i,a]*M[bh,a,c] -----------------
__global__ void __launch_bounds__(256) t_kernel(
    const float* __restrict__ P0, const float* __restrict__ Mm, float* __restrict__ T)
{
    int bh = blockIdx.y;
    int i0 = blockIdx.x * 64;
    __shared__ float Ms[64 * 64];
    __shared__ float Ps[64 * 64];
    int tid = threadIdx.x;
    const float* Mp = Mm + (size_t)bh * 4096;
    const float* Pp = P0 + ((size_t)bh * SDIM + i0) * DDIM;
#pragma unroll
    for (int l = 0; l < 4; l++) {
        int idx = tid + l * 256;
        ((float4*)Ms)[idx] = ((const float4*)Mp)[idx];
        ((float4*)Ps)[idx] = ((const float4*)Pp)[idx];
    }
    __syncthreads();
    int row = tid >> 2, cq = tid & 3;
    float acc[16];
#pragma unroll
    for (int j = 0; j < 16; j++) acc[j] = 0.f;
    for (int a = 0; a < 64; a++) {
        float pa = Ps[row * 64 + a];
#pragma unroll
        for (int j = 0; j < 16; j++) acc[j] += pa * Ms[a * 64 + cq * 16 + j];
    }
    float* Tp = T + ((size_t)bh * SDIM + i0) * DDIM;
#pragma unroll
    for (int j = 0; j < 16; j++) Tp[row * 64 + cq * 16 + j] = acc[j];
}

// ---------------- fused logits (3xtf32 TC) + softmax ---------------------
// block = (bh, 16 rows) x full 1024 cols.  warp w owns cols [c*128+w*16, +16)
#define PSTR 68   // fp32 smem row stride

__global__ void __launch_bounds__(256, 1) lsm_kernel(
    const float* __restrict__ T, const float* __restrict__ P1, float* __restrict__ attn)
{
    __shared__ float Bs[128 * PSTR];
    __shared__ float As[16 * PSTR];
    __shared__ float wmax[8][16];
    __shared__ float wsum[8][16];

    const int bh = blockIdx.y;
    const int m0 = blockIdx.x * 16;
    const int tid = threadIdx.x, lane = tid & 31, w = tid >> 5;
    const int g = lane >> 2, t4 = lane & 3;

    const float* Tp = T  + ((size_t)bh * SDIM + m0) * DDIM;
    const float* Pp = P1 + (size_t)bh * SDIM * DDIM;
    float* Op = attn + ((size_t)bh << 20) + (size_t)m0 * SDIM;

    // load t tile 16x64
    {
        int r = tid >> 4, f4 = tid & 15;
        float4 v = *(const float4*)&Tp[r * 64 + f4 * 4];
        *(float4*)&As[r * PSTR + f4 * 4] = v;
    }
    __syncthreads();

    // precompute A fragments (tf32 hi/lo) for all 8 k-steps
    unsigned ahi[8][4], alo[8][4];
#pragma unroll
    for (int ks = 0; ks < 8; ks++) {
        float a[4];
        a[0] = As[g * PSTR + ks * 8 + t4];
        a[1] = As[(g + 8) * PSTR + ks * 8 + t4];
        a[2] = As[g * PSTR + ks * 8 + t4 + 4];
        a[3] = As[(g + 8) * PSTR + ks * 8 + t4 + 4];
#pragma unroll
        for (int i = 0; i < 4; i++) {
            unsigned h = f2tf(a[i]);
            ahi[ks][i] = h;
            alo[ks][i] = f2tf(a[i] - __uint_as_float(h));
        }
    }

    float acc[8][2][4];
#pragma unroll
    for (int c = 0; c < 8; c++)
#pragma unroll
        for (int nt = 0; nt < 2; nt++)
#pragma unroll
            for (int e = 0; e < 4; e++) acc[c][nt][e] = 0.f;

#pragma unroll 1
    for (int c = 0; c < 8; c++) {
        __syncthreads();
#pragma unroll
        for (int l = 0; l < 8; l++) {
            int idx = l * 256 + tid;
            int row = idx >> 4, f4 = idx & 15;
            float4 v = *(const float4*)&Pp[(size_t)(c * 128 + row) * 64 + f4 * 4];
            *(float4*)&Bs[row * PSTR + f4 * 4] = v;
        }
        __syncthreads();

#pragma unroll
        for (int nt = 0; nt < 2; nt++) {
            int nb = w * 16 + nt * 8 + g;
#pragma unroll
            for (int ks = 0; ks < 8; ks++) {
                float b0 = Bs[nb * PSTR + ks * 8 + t4];
                float b1 = Bs[nb * PSTR + ks * 8 + t4 + 4];
                unsigned bh0 = f2tf(b0), bh1 = f2tf(b1);
                unsigned bl0 = f2tf(b0 - __uint_as_float(bh0));
                unsigned bl1 = f2tf(b1 - __uint_as_float(bh1));
                mma_tf32(acc[c][nt], ahi[ks], bh0, bh1);
                mma_tf32(acc[c][nt], ahi[ks], bl0, bl1);
                mma_tf32(acc[c][nt], alo[ks], bh0, bh1);
            }
        }
    }

    // ---- softmax over full rows ----
    const float SC = 0.125f;
    float mr0 = -1e30f, mr1 = -1e30f;
#pragma unroll
    for (int c = 0; c < 8; c++)
#pragma unroll
        for (int nt = 0; nt < 2; nt++) {
            mr0 = fmaxf(mr0, fmaxf(acc[c][nt][0], acc[c][nt][1]));
            mr1 = fmaxf(mr1, fmaxf(acc[c][nt][2], acc[c][nt][3]));
        }
#pragma unroll
    for (int o = 1; o <= 2; o <<= 1) {
        mr0 = fmaxf(mr0, __shfl_xor_sync(0xffffffffu, mr0, o));
        mr1 = fmaxf(mr1, __shfl_xor_sync(0xffffffffu, mr1, o));
    }
    if (t4 == 0) { wmax[w][g] = mr0; wmax[w][g + 8] = mr1; }
    __syncthreads();
    float M0 = -1e30f, M1 = -1e30f;
#pragma unroll
    for (int ww = 0; ww < 8; ww++) {
        M0 = fmaxf(M0, wmax[ww][g]);
        M1 = fmaxf(M1, wmax[ww][g + 8]);
    }

    float s0 = 0.f, s1 = 0.f;
#pragma unroll
    for (int c = 0; c < 8; c++)
#pragma unroll
        for (int nt = 0; nt < 2; nt++) {
            float e0 = __expf((acc[c][nt][0] - M0) * SC);
            float e1 = __expf((acc[c][nt][1] - M0) * SC);
            float e2 = __expf((acc[c][nt][2] - M1) * SC);
            float e3 = __expf((acc[c][nt][3] - M1) * SC);
            acc[c][nt][0] = e0; acc[c][nt][1] = e1;
            acc[c][nt][2] = e2; acc[c][nt][3] = e3;
            s0 += e0 + e1; s1 += e2 + e3;
        }
#pragma unroll
    for (int o = 1; o <= 2; o <<= 1) {
        s0 += __shfl_xor_sync(0xffffffffu, s0, o);
        s1 += __shfl_xor_sync(0xffffffffu, s1, o);
    }
    if (t4 == 0) { wsum[w][g] = s0; wsum[w][g + 8] = s1; }
    __syncthreads();
    float S0 = 0.f, S1 = 0.f;
#pragma unroll
    for (int ww = 0; ww < 8; ww++) { S0 += wsum[ww][g]; S1 += wsum[ww][g + 8]; }
    float inv0 = 1.0f / S0, inv1 = 1.0f / S1;

#pragma unroll
    for (int c = 0; c < 8; c++)
#pragma unroll
        for (int nt = 0; nt < 2; nt++) {
            int col = c * 128 + w * 16 + nt * 8 + 2 * t4;
            *(float2*)&Op[(size_t)g * SDIM + col] =
                make_float2(acc[c][nt][0] * inv0, acc[c][nt][1] * inv0);
            *(float2*)&Op[(size_t)(g + 8) * SDIM + col] =
                make_float2(acc[c][nt][2] * inv1, acc[c][nt][3] * inv1);
        }
}

// ---------------- V transpose + bf16 split: vT[bh][d][s] -----------------
__global__ void vt_kernel(const float* __restrict__ V,
                          __nv_bfloat16* __restrict__ VH, __nv_bfloat16* __restrict__ VL)
{
    __shared__ float ts[64][65];
    int bh = blockIdx.y;
    int s0 = blockIdx.x * 64;
    int tid = threadIdx.x;
#pragma unroll
    for (int l = 0; l < 4; l++) {
        int idx = l * 256 + tid;
        int s = idx >> 4, f4 = idx & 15;
        float4 v = *(const float4*)&V[((size_t)bh * SDIM + s0 + s) * DDIM + f4 * 4];
        ts[s][f4 * 4 + 0] = v.x; ts[s][f4 * 4 + 1] = v.y;
        ts[s][f4 * 4 + 2] = v.z; ts[s][f4 * 4 + 3] = v.w;
    }
    __syncthreads();
#pragma unroll
    for (int l = 0; l < 4; l++) {
        int idx = l * 256 + tid;
        int d = idx >> 4, sg = (idx & 15) * 4;
        float x0 = ts[sg + 0][d], x1 = ts[sg + 1][d];
        float x2 = ts[sg + 2][d], x3 = ts[sg + 3][d];
        __nv_bfloat16 h0 = __float2bfloat16_rn(x0), h1 = __float2bfloat16_rn(x1);
        __nv_bfloat16 h2 = __float2bfloat16_rn(x2), h3 = __float2bfloat16_rn(x3);
        size_t o = ((size_t)bh * DDIM + d) * SDIM + s0 + sg;
        *(__nv_bfloat162*)&VH[o]     = __nv_bfloat162(h0, h1);
        *(__nv_bfloat162*)&VH[o + 2] = __nv_bfloat162(h2, h3);
        *(__nv_bfloat162*)&VL[o] = __nv_bfloat162(
            __float2bfloat16_rn(x0 - __bfloat162float(h0)),
            __float2bfloat16_rn(x1 - __bfloat162float(h1)));
        *(__nv_bfloat162*)&VL[o + 2] = __nv_bfloat162(
            __float2bfloat16_rn(x2 - __bfloat162float(h2)),
            __float2bfloat16_rn(x3 - __bfloat162float(h3)));
    }
}

// ---------------- AV: values = attn @ V, bf16 split-3 TC ------------------
__global__ void __launch_bounds__(256, 1) av_tc_kernel(
    const float* __restrict__ attn, const __nv_bfloat16* __restrict__ VH,
    const __nv_bfloat16* __restrict__ VL, float* __restrict__ Vals)
{
    __shared__ __nv_bfloat16 Ah[128 * LDSS];
    __shared__ __nv_bfloat16 Al[128 * LDSS];
    __shared__ __nv_bfloat16 Bh[64 * LDSS];
    __shared__ __nv_bfloat16 Bl[64 * LDSS];

    const int bh = blockIdx.y;
    const int bb = bh >> 4, h = bh & 15;
    const int m0 = blockIdx.x * 128;
    const int tid = threadIdx.x, lane = tid & 31, w = tid >> 5;
    const int wm = w * 16;

    const float* Ap = attn + ((size_t)bh << 20) + (size_t)m0 * SDIM;
    const __nv_bfloat16* vhp = VH + (size_t)bh * DDIM * SDIM;
    const __nv_bfloat16* vlp = VL + (size_t)bh * DDIM * SDIM;

    unsigned aoH, aoL, boH[4], boL[4];
    {
        int ar = lane & 15, ak = (lane >> 4) * 8;
        aoH = s2u(Ah) + ((wm + ar) * LDSS + ak) * 2;
        aoL = s2u(Al) + ((wm + ar) * LDSS + ak) * 2;
        int nr = (lane & 7) + ((lane >> 4) & 1) * 8;
        int nk = ((lane >> 3) & 1) * 8;
#pragma unroll
        for (int np = 0; np < 4; np++) {
            boH[np] = s2u(Bh) + ((np * 16 + nr) * LDSS + nk) * 2;
            boL[np] = s2u(Bl) + ((np * 16 + nr) * LDSS + nk) * 2;
        }
    }

    float acc[8][4];
#pragma unroll
    for (int i = 0; i < 8; i++)
#pragma unroll
        for (int e = 0; e < 4; e++) acc[i][e] = 0.f;

#pragma unroll 1
    for (int k0 = 0; k0 < SDIM; k0 += 32) {
#pragma unroll
        for (int l = 0; l < 4; l++) {
            int idx = l * 256 + tid;
            int m = idx >> 3, kq = (idx & 7) * 4;
            float4 v = *(const float4*)&Ap[(size_t)m * SDIM + k0 + kq];
            int o = m * LDSS + kq;
            __nv_bfloat16 h0 = __float2bfloat16_rn(v.x), h1 = __float2bfloat16_rn(v.y);
            __nv_bfloat16 h2 = __float2bfloat16_rn(v.z), h3 = __float2bfloat16_rn(v.w);
            *(__nv_bfloat162*)&Ah[o]     = __nv_bfloat162(h0, h1);
            *(__nv_bfloat162*)&Ah[o + 2] = __nv_bfloat162(h2, h3);
            *(__nv_bfloat162*)&Al[o] = __nv_bfloat162(
                __float2bfloat16_rn(v.x - __bfloat162float(h0)),
                __float2bfloat16_rn(v.y - __bfloat162float(h1)));
            *(__nv_bfloat162*)&Al[o + 2] = __nv_bfloat162(
                __float2bfloat16_rn(v.z - __bfloat162float(h2)),
                __float2bfloat16_rn(v.w - __bfloat162float(h3)));
        }
        {
            int d = tid >> 2, kq = (tid & 3) * 8;
            uint4 hv = *(const uint4*)&vhp[(size_t)d * SDIM + k0 + kq];
            *(uint4*)&Bh[d * LDSS + kq] = hv;
            uint4 lv = *(const uint4*)&vlp[(size_t)d * SDIM + k0 + kq];
            *(uint4*)&Bl[d * LDSS + kq] = lv;
        }
        __syncthreads();

#pragma unroll
        for (int ks = 0; ks < 2; ks++) {
            unsigned off = ks * 32;
            unsigned ah[4], al[4], bhf[8][2], blf[8][2];
            ldsm4(ah, aoH + off);
            ldsm4(al, aoL + off);
#pragma unroll
            for (int np = 0; np < 4; np++) {
                unsigned r[4];
                ldsm4(r, boH[np] + off);
                bhf[2 * np][0] = r[0]; bhf[2 * np][1] = r[1];
                bhf[2 * np + 1][0] = r[2]; bhf[2 * np + 1][1] = r[3];
                ldsm4(r, boL[np] + off);
                blf[2 * np][0] = r[0]; blf[2 * np][1] = r[1];
                blf[2 * np + 1][0] = r[2]; blf[2 * np + 1][1] = r[3];
            }
#pragma unroll
            for (int nt = 0; nt < 8; nt++) {
                mma16816(acc[nt], ah, bhf[nt]);
                mma16816(acc[nt], ah, blf[nt]);
                mma16816(acc[nt], al, bhf[nt]);
            }
        }
        __syncthreads();
    }

    const int g = lane >> 2, cq = (lane & 3) * 2;
#pragma unroll
    for (int nt = 0; nt < 8; nt++) {
        int d = nt * 8 + cq;
        int r0 = m0 + wm + g;
        *(float2*)&Vals[((size_t)(bb * SDIM + r0)) * EDIM + h * DDIM + d] =
            make_float2(acc[nt][0], acc[nt][1]);
        *(float2*)&Vals[((size_t)(bb * SDIM + r0 + 8)) * EDIM + h * DDIM + d] =
            make_float2(acc[nt][2], acc[nt][3]);
    }
}

// ---------------- launch ----------------------------------------------
extern "C" void kernel_launch(void* const* d_in, const int* in_sizes, int n_in,
                              void* d_out, int out_size)
{
    const float* x  = (const float*)d_in[0];
    const float* W0 = (const float*)d_in[1];
    const float* b0 = (const float*)d_in[2];
    const float* W1 = (const float*)d_in[3];
    const float* b1 = (const float*)d_in[4];
    const float* W2 = (const float*)d_in[5];
    const float* b2 = (const float*)d_in[6];
    const float* Wv = (const float*)d_in[7];
    const float* bv = (const float*)d_in[8];
    const float* Wo = (const float*)d_in[9];
    const float* bo = (const float*)d_in[10];
    const float* A  = (const float*)d_in[11];

    float* out  = (float*)d_out;
    float* attn = out + (size_t)MTOT * EDIM;

    float *p0, *p1, *p2, *v, *s2, *Mm, *T, *Vals;
    __nv_bfloat16 *vth, *vtl;
    cudaGetSymbolAddress((void**)&p0, g_p0);
    cudaGetSymbolAddress((void**)&p1, g_p1);
    cudaGetSymbolAddress((void**)&p2, g_p2);
    cudaGetSymbolAddress((void**)&v,  g_v);
    cudaGetSymbolAddress((void**)&s2, g_s2);
    cudaGetSymbolAddress((void**)&Mm, g_M);
    cudaGetSymbolAddress((void**)&T,  g_t);
    cudaGetSymbolAddress((void**)&Vals, g_val);
    cudaGetSymbolAddress((void**)&vth, g_vth);
    cudaGetSymbolAddress((void**)&vtl, g_vtl);

    dim3 gProj(EDIM / 128, MTOT / 128, 4);
    gemm_proj_kernel<<<gProj, 256>>>(x, W0, b0, p0, W1, b1, p1, W2, b2, p2, Wv, bv, v);

    s2_kernel<<<BH, 512>>>(p2, s2);
    m_kernel<<<dim3(64, BH), 64>>>(A, s2, Mm);
    t_kernel<<<dim3(16, BH), 256>>>(p0, Mm, T);
    vt_kernel<<<dim3(16, BH), 256>>>(v, vth, vtl);

    lsm_kernel<<<dim3(64, BH), 256>>>(T, p1, attn);
    av_tc_kernel<<<dim3(8, BH), 256>>>(attn, vth, vtl, Vals);

    gemm_out_kernel<<<dim3(EDIM / 128, MTOT / 128), 256>>>(Vals, Wo, bo, out);
}

// round 5
// speedup vs baseline: 1.9409x; 1.0163x over previous
#include <cuda_runtime.h>
#include <cuda_bf16.h>
#include <math.h>

#define SDIM 1024
#define EDIM 1024
#define BDIM 4
#define HDIM 16
#define DDIM 64
#define BH   64
#define MTOT 4096

typedef __nv_bfloat16  bf16;
typedef __nv_bfloat162 bf162;

// ---------------- scratch (device globals; no allocation) ----------------
__device__ float g_p0[BH * SDIM * DDIM];
__device__ float g_p1[BH * SDIM * DDIM];
__device__ float g_v [BH * SDIM * DDIM];
__device__ float g_s2[BDIM * EDIM];
__device__ float g_M [BH * DDIM * DDIM];
__device__ float g_xsum[BDIM * EDIM];
__device__ bf16 g_xh[MTOT * EDIM],  g_xl[MTOT * EDIM];
__device__ bf16 g_w0h[EDIM * EDIM], g_w0l[EDIM * EDIM];
__device__ bf16 g_w1h[EDIM * EDIM], g_w1l[EDIM * EDIM];
__device__ bf16 g_wvh[EDIM * EDIM], g_wvl[EDIM * EDIM];
__device__ bf16 g_woh[EDIM * EDIM], g_wol[EDIM * EDIM];
__device__ bf16 g_valh[MTOT * EDIM], g_vall[MTOT * EDIM];
__device__ bf16 g_vth[BH * DDIM * SDIM], g_vtl[BH * DDIM * SDIM];

// ---------------- helpers -------------------------------------------------
__device__ __forceinline__ unsigned s2u(const void* p) {
    return (unsigned)__cvta_generic_to_shared(p);
}
__device__ __forceinline__ void ldsm4(unsigned* r, unsigned addr) {
    asm volatile("ldmatrix.sync.aligned.m8n8.x4.shared.b16 {%0,%1,%2,%3}, [%4];"
                 : "=r"(r[0]), "=r"(r[1]), "=r"(r[2]), "=r"(r[3]) : "r"(addr));
}
__device__ __forceinline__ void mma16816(float* c, const unsigned* a, const unsigned* b) {
    asm volatile("mma.sync.aligned.m16n8k16.row.col.f32.bf16.bf16.f32 "
                 "{%0,%1,%2,%3}, {%4,%5,%6,%7}, {%8,%9}, {%0,%1,%2,%3};"
                 : "+f"(c[0]), "+f"(c[1]), "+f"(c[2]), "+f"(c[3])
                 : "r"(a[0]), "r"(a[1]), "r"(a[2]), "r"(a[3]), "r"(b[0]), "r"(b[1]));
}
__device__ __forceinline__ void mma_tf32(float* c, const unsigned* a, unsigned b0, unsigned b1) {
    asm volatile("mma.sync.aligned.m16n8k8.row.col.f32.tf32.tf32.f32 "
                 "{%0,%1,%2,%3}, {%4,%5,%6,%7}, {%8,%9}, {%0,%1,%2,%3};"
                 : "+f"(c[0]), "+f"(c[1]), "+f"(c[2]), "+f"(c[3])
                 : "r"(a[0]), "r"(a[1]), "r"(a[2]), "r"(a[3]), "r"(b0), "r"(b1));
}
__device__ __forceinline__ unsigned f2tf(float x) {
    unsigned r;
    asm("cvt.rna.tf32.f32 %0, %1;" : "=r"(r) : "f"(x));
    return r;
}
__device__ __forceinline__ void cpasync16(unsigned saddr, const void* gaddr) {
    asm volatile("cp.async.cg.shared.global [%0], [%1], 16;" :: "r"(saddr), "l"(gaddr));
}
__device__ __forceinline__ void cpcommit() { asm volatile("cp.async.commit_group;"); }
__device__ __forceinline__ void cpwait1()  { asm volatile("cp.async.wait_group 1;"); }

// ---------------- split fp32 -> bf16 hi/lo --------------------------------
__global__ void split_kernel(const float* __restrict__ X, const float* __restrict__ W0,
                             const float* __restrict__ W1, const float* __restrict__ Wv,
                             const float* __restrict__ Wo)
{
    int z = blockIdx.y;
    size_t base = ((size_t)blockIdx.x * 256 + threadIdx.x) * 4;
    const float* src; bf16 *dh, *dl;
    if (z < 4)      { src = X + ((size_t)z << 20); dh = g_xh + ((size_t)z << 20); dl = g_xl + ((size_t)z << 20); }
    else if (z == 4){ src = W0; dh = g_w0h; dl = g_w0l; }
    else if (z == 5){ src = W1; dh = g_w1h; dl = g_w1l; }
    else if (z == 6){ src = Wv; dh = g_wvh; dl = g_wvl; }
    else            { src = Wo; dh = g_woh; dl = g_wol; }

    float4 v = *(const float4*)&src[base];
    bf16 h0 = __float2bfloat16_rn(v.x), h1 = __float2bfloat16_rn(v.y);
    bf16 h2 = __float2bfloat16_rn(v.z), h3 = __float2bfloat16_rn(v.w);
    *(bf162*)&dh[base]     = bf162(h0, h1);
    *(bf162*)&dh[base + 2] = bf162(h2, h3);
    *(bf162*)&dl[base] = bf162(__float2bfloat16_rn(v.x - __bfloat162float(h0)),
                               __float2bfloat16_rn(v.y - __bfloat162float(h1)));
    *(bf162*)&dl[base + 2] = bf162(__float2bfloat16_rn(v.z - __bfloat162float(h2)),
                                   __float2bfloat16_rn(v.w - __bfloat162float(h3)));
}

// ---------------- xsum[b][e] = sum_s x[b,s,e] -----------------------------
__global__ void xsum_kernel(const float* __restrict__ X)
{
    int b = blockIdx.y;
    int e = blockIdx.x * 256 + threadIdx.x;
    const float* p = X + ((size_t)b * SDIM) * EDIM + e;
    float acc = 0.f;
    for (int s = 0; s < SDIM; s++) acc += p[(size_t)s * EDIM];
    g_xsum[b * EDIM + e] = acc;
}

// ---------------- s2[b*1024+col] = xsum[b] . W2[col] + 1024*b2[col] -------
__global__ void s2small_kernel(const float* __restrict__ W2, const float* __restrict__ b2)
{
    int w = threadIdx.x >> 5, lane = threadIdx.x & 31;
    int b = blockIdx.y;
    int col = blockIdx.x * 8 + w;
    const float* wp = W2 + (size_t)col * EDIM;
    const float* xp = g_xsum + b * EDIM;
    float acc = 0.f;
    for (int e = lane; e < EDIM; e += 32) acc += xp[e] * wp[e];
#pragma unroll
    for (int o = 16; o > 0; o >>= 1) acc += __shfl_xor_sync(0xffffffffu, acc, o);
    if (lane == 0) g_s2[b * EDIM + col] = acc + 1024.0f * b2[col];
}

// ---------------- M[bh,a,c] = sum_d A[a,c,d]*s2[bh,d] --------------------
__global__ void m_kernel(const float* __restrict__ A)
{
    int bh = blockIdx.y, a = blockIdx.x;
    int c = threadIdx.x;
    __shared__ float s2s[64];
    s2s[c] = g_s2[bh * DDIM + c];
    __syncthreads();
    const float* Ap = A + ((size_t)a * DDIM + c) * DDIM;
    float acc = 0.f;
#pragma unroll
    for (int d = 0; d < 64; d++) acc += Ap[d] * s2s[d];
    g_M[(size_t)bh * 4096 + a * DDIM + c] = acc;
}

// ---------------- pipelined bf16 split-3 GEMM (cp.async, 3 stages) --------
#define KT   32
#define LDSS 40
#define STG  3
#define ARR_ELEM (128 * LDSS)
#define ARR_BYTES (ARR_ELEM * 2)
#define STG_BYTES (4 * ARR_BYTES)
#define SMEM_TOTAL_G (STG * STG_BYTES)

template <int MODE>
__device__ __forceinline__ void gemmb_core(
    const bf16* __restrict__ Ah, const bf16* __restrict__ Al,
    const bf16* __restrict__ Bh, const bf16* __restrict__ Bl,
    const float* __restrict__ bias, float* __restrict__ Out)
{
    extern __shared__ bf16 dsm[];
    const unsigned sbase = s2u(dsm);
    const int tid = threadIdx.x, lane = tid & 31, wid = tid >> 5;
    const int m0 = blockIdx.y * 128, n0 = blockIdx.x * 128;
    const int wm = (wid >> 2) * 64, wn = (wid & 3) * 32;

    // cp.async mapping: 2 threads/row, each thread 2 chunks per array
    const int crow = tid >> 1;
    const int ccol = (tid & 1) * 16;
    const bf16* gAh = Ah + (size_t)(m0 + crow) * EDIM + ccol;
    const bf16* gAl = Al + (size_t)(m0 + crow) * EDIM + ccol;
    const bf16* gBh = Bh + (size_t)(n0 + crow) * EDIM + ccol;
    const bf16* gBl = Bl + (size_t)(n0 + crow) * EDIM + ccol;
    const unsigned soff = (crow * LDSS + ccol) * 2;

    auto issue = [&](int stage, int k0) {
        unsigned sb = sbase + stage * STG_BYTES + soff;
        cpasync16(sb,                     gAh + k0);
        cpasync16(sb + 16,                gAh + k0 + 8);
        cpasync16(sb + ARR_BYTES,         gAl + k0);
        cpasync16(sb + ARR_BYTES + 16,    gAl + k0 + 8);
        cpasync16(sb + 2 * ARR_BYTES,     gBh + k0);
        cpasync16(sb + 2 * ARR_BYTES + 16,gBh + k0 + 8);
        cpasync16(sb + 3 * ARR_BYTES,     gBl + k0);
        cpasync16(sb + 3 * ARR_BYTES + 16,gBl + k0 + 8);
    };

    unsigned baA[4], baB[2];
    {
        int ar = lane & 15, ak = (lane >> 4) * 8;
#pragma unroll
        for (int mi = 0; mi < 4; mi++) baA[mi] = ((wm + mi * 16 + ar) * LDSS + ak) * 2;
        int nr = (lane & 7) + ((lane >> 4) & 1) * 8;
        int nk = ((lane >> 3) & 1) * 8;
#pragma unroll
        for (int np = 0; np < 2; np++) baB[np] = ((wn + np * 16 + nr) * LDSS + nk) * 2;
    }

    float acc[4][4][4];
#pragma unroll
    for (int i = 0; i < 4; i++)
#pragma unroll
        for (int j = 0; j < 4; j++)
#pragma unroll
            for (int e = 0; e < 4; e++) acc[i][j][e] = 0.f;

    issue(0, 0); cpcommit();
    issue(1, KT); cpcommit();

    const int NT = EDIM / KT;
    for (int kt = 0; kt < NT; kt++) {
        cpwait1();
        __syncthreads();
        if (kt + 2 < NT) issue((kt + 2) % STG, (kt + 2) * KT);
        cpcommit();

        unsigned sb = sbase + (kt % STG) * STG_BYTES;
#pragma unroll
        for (int kk = 0; kk < 2; kk++) {
            unsigned off = kk * 32;
            unsigned ah[4][4], al[4][4], bh_[4][2], bl_[4][2];
#pragma unroll
            for (int mi = 0; mi < 4; mi++) ldsm4(ah[mi], sb + baA[mi] + off);
#pragma unroll
            for (int np = 0; np < 2; np++) {
                unsigned r[4];
                ldsm4(r, sb + 2 * ARR_BYTES + baB[np] + off);
                bh_[2 * np][0] = r[0]; bh_[2 * np][1] = r[1];
                bh_[2 * np + 1][0] = r[2]; bh_[2 * np + 1][1] = r[3];
            }
#pragma unroll
            for (int mi = 0; mi < 4; mi++)
#pragma unroll
                for (int ni = 0; ni < 4; ni++) mma16816(acc[mi][ni], ah[mi], bh_[ni]);

#pragma unroll
            for (int np = 0; np < 2; np++) {
                unsigned r[4];
                ldsm4(r, sb + 3 * ARR_BYTES + baB[np] + off);
                bl_[2 * np][0] = r[0]; bl_[2 * np][1] = r[1];
                bl_[2 * np + 1][0] = r[2]; bl_[2 * np + 1][1] = r[3];
            }
#pragma unroll
            for (int mi = 0; mi < 4; mi++)
#pragma unroll
                for (int ni = 0; ni < 4; ni++) mma16816(acc[mi][ni], ah[mi], bl_[ni]);

#pragma unroll
            for (int mi = 0; mi < 4; mi++) ldsm4(al[mi], sb + ARR_BYTES + baA[mi] + off);
#pragma unroll
            for (int mi = 0; mi < 4; mi++)
#pragma unroll
                for (int ni = 0; ni < 4; ni++) mma16816(acc[mi][ni], al[mi], bh_[ni]);
        }
    }

    const int g = lane >> 2;
    const int cq = (lane & 3) * 2;
#pragma unroll
    for (int mi = 0; mi < 4; mi++) {
#pragma unroll
        for (int ni = 0; ni < 4; ni++) {
            int col = n0 + wn + ni * 8 + cq;
            float2 bia = *(const float2*)&bias[col];
#pragma unroll
            for (int half = 0; half < 2; half++) {
                int row = m0 + wm + mi * 16 + g + half * 8;
                float v0 = acc[mi][ni][half * 2 + 0] + bia.x;
                float v1 = acc[mi][ni][half * 2 + 1] + bia.y;
                if (MODE == 0) {
                    int bb = row >> 10, ss = row & 1023;
                    int h = col >> 6, d = col & 63;
                    *(float2*)&Out[(((size_t)(bb * HDIM + h) * SDIM) + ss) * DDIM + d]
                        = make_float2(v0, v1);
                } else {
                    *(float2*)&Out[(size_t)row * EDIM + col] = make_float2(v0, v1);
                }
            }
        }
    }
}

__global__ void __launch_bounds__(256, 1) gemmb_proj_kernel(
    const float* __restrict__ b0, const float* __restrict__ b1, const float* __restrict__ bv)
{
    switch (blockIdx.z) {
        case 0:  gemmb_core<0>(g_xh, g_xl, g_w0h, g_w0l, b0, g_p0); break;
        case 1:  gemmb_core<0>(g_xh, g_xl, g_w1h, g_w1l, b1, g_p1); break;
        default: gemmb_core<0>(g_xh, g_xl, g_wvh, g_wvl, bv, g_v);  break;
    }
}

__global__ void __launch_bounds__(256, 1) gemmb_out_kernel(
    const float* __restrict__ bo, float* __restrict__ Out)
{
    gemmb_core<1>(g_valh, g_vall, g_woh, g_wol, bo, Out);
}

// ---------------- fused t-compute + logits (3xtf32) + softmax -------------
#define PSTR 68

__global__ void __launch_bounds__(256, 1) lsm_kernel(float* __restrict__ attn)
{
    __shared__ float Bs[128 * PSTR];
    __shared__ float As[16 * PSTR];
    __shared__ float wmax[8][16];
    __shared__ float wsum[8][16];

    const int bh = blockIdx.y;
    const int m0 = blockIdx.x * 16;
    const int tid = threadIdx.x, lane = tid & 31, w = tid >> 5;
    const int g = lane >> 2, t4 = lane & 3;

    const float* Pp = g_p1 + (size_t)bh * SDIM * DDIM;
    float* Op = attn + ((size_t)bh << 20) + (size_t)m0 * SDIM;

    // ---- prologue: t = p0_tile(16x64) @ M(64x64), M staged through Bs ----
    {
        const float* Mp = g_M + (size_t)bh * 4096;
#pragma unroll
        for (int l = 0; l < 4; l++) {
            int idx = l * 256 + tid;
            int row = idx >> 4, c4 = (idx & 15) * 4;
            *(float4*)&Bs[row * PSTR + c4] = *(const float4*)&Mp[row * 64 + c4];
        }
        const float* P0p = g_p0 + ((size_t)bh * SDIM + m0) * DDIM;
        int r = tid >> 4, f4 = (tid & 15) * 4;
        *(float4*)&As[r * PSTR + f4] = *(const float4*)&P0p[r * 64 + f4];
    }
    __syncthreads();
    {
        int r = tid >> 4, c4 = (tid & 15) * 4;
        float4 tacc = make_float4(0.f, 0.f, 0.f, 0.f);
#pragma unroll 8
        for (int a = 0; a < 64; a++) {
            float pa = As[r * PSTR + a];
            float4 m = *(float4*)&Bs[a * PSTR + c4];
            tacc.x += pa * m.x; tacc.y += pa * m.y;
            tacc.z += pa * m.z; tacc.w += pa * m.w;
        }
        __syncthreads();
        *(float4*)&As[r * PSTR + c4] = tacc;
    }
    __syncthreads();

    // precompute A fragments (tf32 hi/lo) for all 8 k-steps
    unsigned ahi[8][4], alo[8][4];
#pragma unroll
    for (int ks = 0; ks < 8; ks++) {
        float a[4];
        a[0] = As[g * PSTR + ks * 8 + t4];
        a[1] = As[(g + 8) * PSTR + ks * 8 + t4];
        a[2] = As[g * PSTR + ks * 8 + t4 + 4];
        a[3] = As[(g + 8) * PSTR + ks * 8 + t4 + 4];
#pragma unroll
        for (int i = 0; i < 4; i++) {
            unsigned h = f2tf(a[i]);
            ahi[ks][i] = h;
            alo[ks][i] = f2tf(a[i] - __uint_as_float(h));
        }
    }

    float acc[8][2][4];
#pragma unroll
    for (int c = 0; c < 8; c++)
#pragma unroll
        for (int nt = 0; nt < 2; nt++)
#pragma unroll
            for (int e = 0; e < 4; e++) acc[c][nt][e] = 0.f;

#pragma unroll 1
    for (int c = 0; c < 8; c++) {
        __syncthreads();
#pragma unroll
        for (int l = 0; l < 8; l++) {
            int idx = l * 256 + tid;
            int row = idx >> 4, f4 = idx & 15;
            float4 v = *(const float4*)&Pp[(size_t)(c * 128 + row) * 64 + f4 * 4];
            *(float4*)&Bs[row * PSTR + f4 * 4] = v;
        }
        __syncthreads();

#pragma unroll
        for (int nt = 0; nt < 2; nt++) {
            int nb = w * 16 + nt * 8 + g;
#pragma unroll
            for (int ks = 0; ks < 8; ks++) {
                float b0 = Bs[nb * PSTR + ks * 8 + t4];
                float b1 = Bs[nb * PSTR + ks * 8 + t4 + 4];
                unsigned bh0 = f2tf(b0), bh1 = f2tf(b1);
                unsigned bl0 = f2tf(b0 - __uint_as_float(bh0));
                unsigned bl1 = f2tf(b1 - __uint_as_float(bh1));
                mma_tf32(acc[c][nt], ahi[ks], bh0, bh1);
                mma_tf32(acc[c][nt], ahi[ks], bl0, bl1);
                mma_tf32(acc[c][nt], alo[ks], bh0, bh1);
            }
        }
    }

    // ---- softmax over full rows ----
    const float SC = 0.125f;
    float mr0 = -1e30f, mr1 = -1e30f;
#pragma unroll
    for (int c = 0; c < 8; c++)
#pragma unroll
        for (int nt = 0; nt < 2; nt++) {
            mr0 = fmaxf(mr0, fmaxf(acc[c][nt][0], acc[c][nt][1]));
            mr1 = fmaxf(mr1, fmaxf(acc[c][nt][2], acc[c][nt][3]));
        }
#pragma unroll
    for (int o = 1; o <= 2; o <<= 1) {
        mr0 = fmaxf(mr0, __shfl_xor_sync(0xffffffffu, mr0, o));
        mr1 = fmaxf(mr1, __shfl_xor_sync(0xffffffffu, mr1, o));
    }
    if (t4 == 0) { wmax[w][g] = mr0; wmax[w][g + 8] = mr1; }
    __syncthreads();
    float M0 = -1e30f, M1 = -1e30f;
#pragma unroll
    for (int ww = 0; ww < 8; ww++) {
        M0 = fmaxf(M0, wmax[ww][g]);
        M1 = fmaxf(M1, wmax[ww][g + 8]);
    }

    float s0 = 0.f, s1 = 0.f;
#pragma unroll
    for (int c = 0; c < 8; c++)
#pragma unroll
        for (int nt = 0; nt < 2; nt++) {
            float e0 = __expf((acc[c][nt][0] - M0) * SC);
            float e1 = __expf((acc[c][nt][1] - M0) * SC);
            float e2 = __expf((acc[c][nt][2] - M1) * SC);
            float e3 = __expf((acc[c][nt][3] - M1) * SC);
            acc[c][nt][0] = e0; acc[c][nt][1] = e1;
            acc[c][nt][2] = e2; acc[c][nt][3] = e3;
            s0 += e0 + e1; s1 += e2 + e3;
        }
#pragma unroll
    for (int o = 1; o <= 2; o <<= 1) {
        s0 += __shfl_xor_sync(0xffffffffu, s0, o);
        s1 += __shfl_xor_sync(0xffffffffu, s1, o);
    }
    if (t4 == 0) { wsum[w][g] = s0; wsum[w][g + 8] = s1; }
    __syncthreads();
    float S0 = 0.f, S1 = 0.f;
#pragma unroll
    for (int ww = 0; ww < 8; ww++) { S0 += wsum[ww][g]; S1 += wsum[ww][g + 8]; }
    float inv0 = 1.0f / S0, inv1 = 1.0f / S1;

#pragma unroll
    for (int c = 0; c < 8; c++)
#pragma unroll
        for (int nt = 0; nt < 2; nt++) {
            int col = c * 128 + w * 16 + nt * 8 + 2 * t4;
            *(float2*)&Op[(size_t)g * SDIM + col] =
                make_float2(acc[c][nt][0] * inv0, acc[c][nt][1] * inv0);
            *(float2*)&Op[(size_t)(g + 8) * SDIM + col] =
                make_float2(acc[c][nt][2] * inv1, acc[c][nt][3] * inv1);
        }
}

// ---------------- V transpose + bf16 split: vT[bh][d][s] -----------------
__global__ void vt_kernel()
{
    __shared__ float ts[64][65];
    int bh = blockIdx.y;
    int s0 = blockIdx.x * 64;
    int tid = threadIdx.x;
#pragma unroll
    for (int l = 0; l < 4; l++) {
        int idx = l * 256 + tid;
        int s = idx >> 4, f4 = idx & 15;
        float4 v = *(const float4*)&g_v[((size_t)bh * SDIM + s0 + s) * DDIM + f4 * 4];
        ts[s][f4 * 4 + 0] = v.x; ts[s][f4 * 4 + 1] = v.y;
        ts[s][f4 * 4 + 2] = v.z; ts[s][f4 * 4 + 3] = v.w;
    }
    __syncthreads();
#pragma unroll
    for (int l = 0; l < 4; l++) {
        int idx = l * 256 + tid;
        int d = idx >> 4, sg = (idx & 15) * 4;
        float x0 = ts[sg + 0][d], x1 = ts[sg + 1][d];
        float x2 = ts[sg + 2][d], x3 = ts[sg + 3][d];
        bf16 h0 = __float2bfloat16_rn(x0), h1 = __float2bfloat16_rn(x1);
        bf16 h2 = __float2bfloat16_rn(x2), h3 = __float2bfloat16_rn(x3);
        size_t o = ((size_t)bh * DDIM + d) * SDIM + s0 + sg;
        *(bf162*)&g_vth[o]     = bf162(h0, h1);
        *(bf162*)&g_vth[o + 2] = bf162(h2, h3);
        *(bf162*)&g_vtl[o] = bf162(__float2bfloat16_rn(x0 - __bfloat162float(h0)),
                                   __float2bfloat16_rn(x1 - __bfloat162float(h1)));
        *(bf162*)&g_vtl[o + 2] = bf162(__float2bfloat16_rn(x2 - __bfloat162float(h2)),
                                       __float2bfloat16_rn(x3 - __bfloat162float(h3)));
    }
}

// ---------------- AV: values = attn @ V, bf16 split-3 TC ------------------
__global__ void __launch_bounds__(256, 1) av_tc_kernel(const float* __restrict__ attn)
{
    __shared__ bf16 Ah[128 * LDSS];
    __shared__ bf16 Al[128 * LDSS];
    __shared__ bf16 Bh[64 * LDSS];
    __shared__ bf16 Bl[64 * LDSS];

    const int bh = blockIdx.y;
    const int bb = bh >> 4, h = bh & 15;
    const int m0 = blockIdx.x * 128;
    const int tid = threadIdx.x, lane = tid & 31, w = tid >> 5;
    const int wm = w * 16;

    const float* Ap = attn + ((size_t)bh << 20) + (size_t)m0 * SDIM;
    const bf16* vhp = g_vth + (size_t)bh * DDIM * SDIM;
    const bf16* vlp = g_vtl + (size_t)bh * DDIM * SDIM;

    unsigned aoH, aoL, boH[4], boL[4];
    {
        int ar = lane & 15, ak = (lane >> 4) * 8;
        aoH = s2u(Ah) + ((wm + ar) * LDSS + ak) * 2;
        aoL = s2u(Al) + ((wm + ar) * LDSS + ak) * 2;
        int nr = (lane & 7) + ((lane >> 4) & 1) * 8;
        int nk = ((lane >> 3) & 1) * 8;
#pragma unroll
        for (int np = 0; np < 4; np++) {
            boH[np] = s2u(Bh) + ((np * 16 + nr) * LDSS + nk) * 2;
            boL[np] = s2u(Bl) + ((np * 16 + nr) * LDSS + nk) * 2;
        }
    }

    float acc[8][4];
#pragma unroll
    for (int i = 0; i < 8; i++)
#pragma unroll
        for (int e = 0; e < 4; e++) acc[i][e] = 0.f;

#pragma unroll 1
    for (int k0 = 0; k0 < SDIM; k0 += 32) {
#pragma unroll
        for (int l = 0; l < 4; l++) {
            int idx = l * 256 + tid;
            int m = idx >> 3, kq = (idx & 7) * 4;
            float4 v = *(const float4*)&Ap[(size_t)m * SDIM + k0 + kq];
            int o = m * LDSS + kq;
            bf16 h0 = __float2bfloat16_rn(v.x), h1 = __float2bfloat16_rn(v.y);
            bf16 h2 = __float2bfloat16_rn(v.z), h3 = __float2bfloat16_rn(v.w);
            *(bf162*)&Ah[o]     = bf162(h0, h1);
            *(bf162*)&Ah[o + 2] = bf162(h2, h3);
            *(bf162*)&Al[o] = bf162(__float2bfloat16_rn(v.x - __bfloat162float(h0)),
                                    __float2bfloat16_rn(v.y - __bfloat162float(h1)));
            *(bf162*)&Al[o + 2] = bf162(__float2bfloat16_rn(v.z - __bfloat162float(h2)),
                                        __float2bfloat16_rn(v.w - __bfloat162float(h3)));
        }
        {
            int d = tid >> 2, kq = (tid & 3) * 8;
            uint4 hv = *(const uint4*)&vhp[(size_t)d * SDIM + k0 + kq];
            *(uint4*)&Bh[d * LDSS + kq] = hv;
            uint4 lv = *(const uint4*)&vlp[(size_t)d * SDIM + k0 + kq];
            *(uint4*)&Bl[d * LDSS + kq] = lv;
        }
        __syncthreads();

#pragma unroll
        for (int ks = 0; ks < 2; ks++) {
            unsigned off = ks * 32;
            unsigned ah[4], al[4], bhf[8][2], blf[8][2];
            ldsm4(ah, aoH + off);
            ldsm4(al, aoL + off);
#pragma unroll
            for (int np = 0; np < 4; np++) {
                unsigned r[4];
                ldsm4(r, boH[np] + off);
                bhf[2 * np][0] = r[0]; bhf[2 * np][1] = r[1];
                bhf[2 * np + 1][0] = r[2]; bhf[2 * np + 1][1] = r[3];
                ldsm4(r, boL[np] + off);
                blf[2 * np][0] = r[0]; blf[2 * np][1] = r[1];
                blf[2 * np + 1][0] = r[2]; blf[2 * np + 1][1] = r[3];
            }
#pragma unroll
            for (int nt = 0; nt < 8; nt++) {
                mma16816(acc[nt], ah, bhf[nt]);
                mma16816(acc[nt], ah, blf[nt]);
                mma16816(acc[nt], al, bhf[nt]);
            }
        }
        __syncthreads();
    }

    // epilogue: write Vals as bf16 hi/lo split (feeds out-GEMM directly)
    const int g = lane >> 2, cq = (lane & 3) * 2;
#pragma unroll
    for (int nt = 0; nt < 8; nt++) {
        int col = h * DDIM + nt * 8 + cq;
        int r0 = m0 + wm + g;
#pragma unroll
        for (int half = 0; half < 2; half++) {
            size_t idx = ((size_t)(bb * SDIM + r0 + half * 8)) * EDIM + col;
            float v0 = acc[nt][half * 2 + 0], v1 = acc[nt][half * 2 + 1];
            bf16 h0 = __float2bfloat16_rn(v0), h1 = __float2bfloat16_rn(v1);
            *(bf162*)&g_valh[idx] = bf162(h0, h1);
            *(bf162*)&g_vall[idx] = bf162(__float2bfloat16_rn(v0 - __bfloat162float(h0)),
                                          __float2bfloat16_rn(v1 - __bfloat162float(h1)));
        }
    }
}

// ---------------- launch ----------------------------------------------
extern "C" void kernel_launch(void* const* d_in, const int* in_sizes, int n_in,
                              void* d_out, int out_size)
{
    const float* x  = (const float*)d_in[0];
    const float* W0 = (const float*)d_in[1];
    const float* b0 = (const float*)d_in[2];
    const float* W1 = (const float*)d_in[3];
    const float* b1 = (const float*)d_in[4];
    const float* W2 = (const float*)d_in[5];
    const float* b2 = (const float*)d_in[6];
    const float* Wv = (const float*)d_in[7];
    const float* bv = (const float*)d_in[8];
    const float* Wo = (const float*)d_in[9];
    const float* bo = (const float*)d_in[10];
    const float* A  = (const float*)d_in[11];

    float* out  = (float*)d_out;
    float* attn = out + (size_t)MTOT * EDIM;

    cudaFuncSetAttribute(gemmb_proj_kernel,
                         cudaFuncAttributeMaxDynamicSharedMemorySize, SMEM_TOTAL_G);
    cudaFuncSetAttribute(gemmb_out_kernel,
                         cudaFuncAttributeMaxDynamicSharedMemorySize, SMEM_TOTAL_G);

    split_kernel<<<dim3(1024, 8), 256>>>(x, W0, W1, Wv, Wo);
    xsum_kernel<<<dim3(4, 4), 256>>>(x);

    gemmb_proj_kernel<<<dim3(8, 32, 3), 256, SMEM_TOTAL_G>>>(b0, b1, bv);

    s2small_kernel<<<dim3(128, 4), 256>>>(W2, b2);
    m_kernel<<<dim3(64, BH), 64>>>(A);
    vt_kernel<<<dim3(16, BH), 256>>>();

    lsm_kernel<<<dim3(64, BH), 256>>>(attn);
    av_tc_kernel<<<dim3(8, BH), 256>>>(attn);

    gemmb_out_kernel<<<dim3(8, 32), 256, SMEM_TOTAL_G>>>(bo, out);
}

// round 6
// speedup vs baseline: 2.0178x; 1.0396x over previous
#include <cuda_runtime.h>
#include <cuda_bf16.h>
#include <math.h>

#define SDIM 1024
#define EDIM 1024
#define BDIM 4
#define HDIM 16
#define DDIM 64
#define BH   64
#define MTOT 4096

typedef __nv_bfloat16  bf16;
typedef __nv_bfloat162 bf162;

// ---------------- scratch (device globals; no allocation) ----------------
__device__ float g_p0[BH * SDIM * DDIM];
__device__ float g_p1[BH * SDIM * DDIM];
__device__ float g_v [BH * SDIM * DDIM];
__device__ float g_s2[BDIM * EDIM];
__device__ float g_M [BH * DDIM * DDIM];
__device__ float g_xsum[BDIM * EDIM];
__device__ float g_val[MTOT * EDIM];
__device__ bf16 g_vth[BH * DDIM * SDIM], g_vtl[BH * DDIM * SDIM];

// ---------------- helpers -------------------------------------------------
__device__ __forceinline__ unsigned s2u(const void* p) {
    return (unsigned)__cvta_generic_to_shared(p);
}
__device__ __forceinline__ void ldsm4(unsigned* r, unsigned addr) {
    asm volatile("ldmatrix.sync.aligned.m8n8.x4.shared.b16 {%0,%1,%2,%3}, [%4];"
                 : "=r"(r[0]), "=r"(r[1]), "=r"(r[2]), "=r"(r[3]) : "r"(addr));
}
__device__ __forceinline__ void mma16816(float* c, const unsigned* a, const unsigned* b) {
    asm volatile("mma.sync.aligned.m16n8k16.row.col.f32.bf16.bf16.f32 "
                 "{%0,%1,%2,%3}, {%4,%5,%6,%7}, {%8,%9}, {%0,%1,%2,%3};"
                 : "+f"(c[0]), "+f"(c[1]), "+f"(c[2]), "+f"(c[3])
                 : "r"(a[0]), "r"(a[1]), "r"(a[2]), "r"(a[3]), "r"(b[0]), "r"(b[1]));
}
__device__ __forceinline__ void mma_tf32(float* c, const unsigned* a, unsigned b0, unsigned b1) {
    asm volatile("mma.sync.aligned.m16n8k8.row.col.f32.tf32.tf32.f32 "
                 "{%0,%1,%2,%3}, {%4,%5,%6,%7}, {%8,%9}, {%0,%1,%2,%3};"
                 : "+f"(c[0]), "+f"(c[1]), "+f"(c[2]), "+f"(c[3])
                 : "r"(a[0]), "r"(a[1]), "r"(a[2]), "r"(a[3]), "r"(b0), "r"(b1));
}
__device__ __forceinline__ unsigned f2tf(float x) {
    unsigned r;
    asm("cvt.rna.tf32.f32 %0, %1;" : "=r"(r) : "f"(x));
    return r;
}

// ---------------- xsum[b][e] = sum_s x[b,s,e] -----------------------------
__global__ void xsum_kernel(const float* __restrict__ X)
{
    int b = blockIdx.y;
    int e = blockIdx.x * 256 + threadIdx.x;
    const float* p = X + ((size_t)b * SDIM) * EDIM + e;
    float acc = 0.f;
    for (int s = 0; s < SDIM; s++) acc += p[(size_t)s * EDIM];
    g_xsum[b * EDIM + e] = acc;
}

// ---------------- s2[b*1024+col] = xsum[b] . W2[col] + 1024*b2[col] -------
__global__ void s2small_kernel(const float* __restrict__ W2, const float* __restrict__ b2)
{
    int w = threadIdx.x >> 5, lane = threadIdx.x & 31;
    int b = blockIdx.y;
    int col = blockIdx.x * 8 + w;
    const float* wp = W2 + (size_t)col * EDIM;
    const float* xp = g_xsum + b * EDIM;
    float acc = 0.f;
    for (int e = lane; e < EDIM; e += 32) acc += xp[e] * wp[e];
#pragma unroll
    for (int o = 16; o > 0; o >>= 1) acc += __shfl_xor_sync(0xffffffffu, acc, o);
    if (lane == 0) g_s2[b * EDIM + col] = acc + 1024.0f * b2[col];
}

// ---------------- M[bh,a,c] = sum_d A[a,c,d]*s2[bh,d] --------------------
__global__ void m_kernel(const float* __restrict__ A)
{
    int bh = blockIdx.y, a = blockIdx.x;
    int c = threadIdx.x;
    __shared__ float s2s[64];
    s2s[c] = g_s2[bh * DDIM + c];
    __syncthreads();
    const float* Ap = A + ((size_t)a * DDIM + c) * DDIM;
    float acc = 0.f;
#pragma unroll
    for (int d = 0; d < 64; d++) acc += Ap[d] * s2s[d];
    g_M[(size_t)bh * 4096 + a * DDIM + c] = acc;
}

// ---------------- proven tensor-core NT GEMM (bf16 split-3, R4) -----------
#define KT    32
#define LDSS  40

template <int MODE>
__device__ __forceinline__ void gemm_core(
    const float* __restrict__ X, const float* __restrict__ W,
    const float* __restrict__ bias, float* __restrict__ Out)
{
    __shared__ bf16 Ah[128 * LDSS];
    __shared__ bf16 Al[128 * LDSS];
    __shared__ bf16 Bh[128 * LDSS];
    __shared__ bf16 Bl[128 * LDSS];

    const int tid  = threadIdx.x;
    const int lane = tid & 31;
    const int wid  = tid >> 5;
    const int m0 = blockIdx.y * 128;
    const int n0 = blockIdx.x * 128;
    const int wm = (wid >> 2) * 64;
    const int wn = (wid & 3) * 32;

    float4 pa[4], pb[4];

    unsigned baA[4], baAl[4], baB[2], baBl[2];
    {
        int ar = lane & 15, ak = (lane >> 4) * 8;
#pragma unroll
        for (int mi = 0; mi < 4; mi++) {
            int off = ((wm + mi * 16 + ar) * LDSS + ak) * 2;
            baA[mi]  = s2u(Ah) + off;
            baAl[mi] = s2u(Al) + off;
        }
        int nr = (lane & 7) + ((lane >> 4) & 1) * 8;
        int nk = ((lane >> 3) & 1) * 8;
#pragma unroll
        for (int np = 0; np < 2; np++) {
            int off = ((wn + np * 16 + nr) * LDSS + nk) * 2;
            baB[np]  = s2u(Bh) + off;
            baBl[np] = s2u(Bl) + off;
        }
    }

    float acc[4][4][4];
#pragma unroll
    for (int i = 0; i < 4; i++)
#pragma unroll
        for (int j = 0; j < 4; j++)
#pragma unroll
            for (int e = 0; e < 4; e++) acc[i][j][e] = 0.f;

    auto loadTile = [&](int k0) {
#pragma unroll
        for (int l = 0; l < 4; l++) {
            int idx = l * 256 + tid;
            int row = idx >> 3, kq = (idx & 7) * 4;
            pa[l] = *(const float4*)&X[(size_t)(m0 + row) * EDIM + k0 + kq];
            pb[l] = *(const float4*)&W[(size_t)(n0 + row) * EDIM + k0 + kq];
        }
    };
    auto storeTile = [&]() {
#pragma unroll
        for (int l = 0; l < 4; l++) {
            int idx = l * 256 + tid;
            int row = idx >> 3, kq = (idx & 7) * 4;
            int o = row * LDSS + kq;
            float4 a = pa[l];
            bf16 hx = __float2bfloat16_rn(a.x);
            bf16 hy = __float2bfloat16_rn(a.y);
            bf16 hz = __float2bfloat16_rn(a.z);
            bf16 hw = __float2bfloat16_rn(a.w);
            *(bf162*)&Ah[o]     = bf162(hx, hy);
            *(bf162*)&Ah[o + 2] = bf162(hz, hw);
            *(bf162*)&Al[o]     = bf162(
                __float2bfloat16_rn(a.x - __bfloat162float(hx)),
                __float2bfloat16_rn(a.y - __bfloat162float(hy)));
            *(bf162*)&Al[o + 2] = bf162(
                __float2bfloat16_rn(a.z - __bfloat162float(hz)),
                __float2bfloat16_rn(a.w - __bfloat162float(hw)));
            float4 b = pb[l];
            hx = __float2bfloat16_rn(b.x); hy = __float2bfloat16_rn(b.y);
            hz = __float2bfloat16_rn(b.z); hw = __float2bfloat16_rn(b.w);
            *(bf162*)&Bh[o]     = bf162(hx, hy);
            *(bf162*)&Bh[o + 2] = bf162(hz, hw);
            *(bf162*)&Bl[o]     = bf162(
                __float2bfloat16_rn(b.x - __bfloat162float(hx)),
                __float2bfloat16_rn(b.y - __bfloat162float(hy)));
            *(bf162*)&Bl[o + 2] = bf162(
                __float2bfloat16_rn(b.z - __bfloat162float(hz)),
                __float2bfloat16_rn(b.w - __bfloat162float(hw)));
        }
    };

    loadTile(0);
    storeTile();
    __syncthreads();

    for (int kt = 0; kt < EDIM / KT; kt++) {
        bool has_next = (kt + 1) < EDIM / KT;
        if (has_next) loadTile((kt + 1) * KT);

#pragma unroll
        for (int kk = 0; kk < 2; kk++) {
            unsigned boff = kk * 32;
            unsigned ah[4][4], al[4][4], bh_[4][2], bl_[4][2];
#pragma unroll
            for (int mi = 0; mi < 4; mi++) ldsm4(ah[mi], baA[mi] + boff);
#pragma unroll
            for (int np = 0; np < 2; np++) {
                unsigned r[4];
                ldsm4(r, baB[np] + boff);
                bh_[2 * np][0] = r[0]; bh_[2 * np][1] = r[1];
                bh_[2 * np + 1][0] = r[2]; bh_[2 * np + 1][1] = r[3];
            }
#pragma unroll
            for (int mi = 0; mi < 4; mi++)
#pragma unroll
                for (int ni = 0; ni < 4; ni++) mma16816(acc[mi][ni], ah[mi], bh_[ni]);

#pragma unroll
            for (int np = 0; np < 2; np++) {
                unsigned r[4];
                ldsm4(r, baBl[np] + boff);
                bl_[2 * np][0] = r[0]; bl_[2 * np][1] = r[1];
                bl_[2 * np + 1][0] = r[2]; bl_[2 * np + 1][1] = r[3];
            }
#pragma unroll
            for (int mi = 0; mi < 4; mi++)
#pragma unroll
                for (int ni = 0; ni < 4; ni++) mma16816(acc[mi][ni], ah[mi], bl_[ni]);

#pragma unroll
            for (int mi = 0; mi < 4; mi++) ldsm4(al[mi], baAl[mi] + boff);
#pragma unroll
            for (int mi = 0; mi < 4; mi++)
#pragma unroll
                for (int ni = 0; ni < 4; ni++) mma16816(acc[mi][ni], al[mi], bh_[ni]);
        }

        __syncthreads();
        if (has_next) {
            storeTile();
            __syncthreads();
        }
    }

    const int g = lane >> 2;
    const int cq = (lane & 3) * 2;
#pragma unroll
    for (int mi = 0; mi < 4; mi++) {
#pragma unroll
        for (int ni = 0; ni < 4; ni++) {
            int col = n0 + wn + ni * 8 + cq;
            float2 bia = *(const float2*)&bias[col];
#pragma unroll
            for (int half = 0; half < 2; half++) {
                int row = m0 + wm + mi * 16 + g + half * 8;
                float v0 = acc[mi][ni][half * 2 + 0] + bia.x;
                float v1 = acc[mi][ni][half * 2 + 1] + bia.y;
                if (MODE == 0) {
                    int bb = row >> 10, ss = row & 1023;
                    int h = col >> 6, d = col & 63;
                    *(float2*)&Out[(((size_t)(bb * HDIM + h) * SDIM) + ss) * DDIM + d]
                        = make_float2(v0, v1);
                } else {
                    *(float2*)&Out[(size_t)row * EDIM + col] = make_float2(v0, v1);
                }
            }
        }
    }
}

__global__ void __launch_bounds__(256, 1) gemm_proj_kernel(
    const float* __restrict__ X,
    const float* __restrict__ W0, const float* __restrict__ b0,
    const float* __restrict__ W1, const float* __restrict__ b1,
    const float* __restrict__ Wv, const float* __restrict__ bv)
{
    switch (blockIdx.z) {
        case 0:  gemm_core<0>(X, W0, b0, g_p0); break;
        case 1:  gemm_core<0>(X, W1, b1, g_p1); break;
        default: gemm_core<0>(X, Wv, bv, g_v);  break;
    }
}

__global__ void __launch_bounds__(256, 1) gemm_out_kernel(
    const float* __restrict__ Wo, const float* __restrict__ bo, float* __restrict__ Out)
{
    gemm_core<1>(g_val, Wo, bo, Out);
}

// ---------------- fused t-compute + logits (3xtf32) + softmax -------------
#define PSTR 68

__global__ void __launch_bounds__(256, 1) lsm_kernel(float* __restrict__ attn)
{
    __shared__ float Bs[128 * PSTR];
    __shared__ float As[16 * PSTR];
    __shared__ float wmax[8][16];
    __shared__ float wsum[8][16];

    const int bh = blockIdx.y;
    const int m0 = blockIdx.x * 16;
    const int tid = threadIdx.x, lane = tid & 31, w = tid >> 5;
    const int g = lane >> 2, t4 = lane & 3;

    const float* Pp = g_p1 + (size_t)bh * SDIM * DDIM;
    float* Op = attn + ((size_t)bh << 20) + (size_t)m0 * SDIM;

    // ---- prologue: t = p0_tile(16x64) @ M(64x64), M staged through Bs ----
    {
        const float* Mp = g_M + (size_t)bh * 4096;
#pragma unroll
        for (int l = 0; l < 4; l++) {
            int idx = l * 256 + tid;
            int row = idx >> 4, c4 = (idx & 15) * 4;
            *(float4*)&Bs[row * PSTR + c4] = *(const float4*)&Mp[row * 64 + c4];
        }
        const float* P0p = g_p0 + ((size_t)bh * SDIM + m0) * DDIM;
        int r = tid >> 4, f4 = (tid & 15) * 4;
        *(float4*)&As[r * PSTR + f4] = *(const float4*)&P0p[r * 64 + f4];
    }
    __syncthreads();
    {
        int r = tid >> 4, c4 = (tid & 15) * 4;
        float4 tacc = make_float4(0.f, 0.f, 0.f, 0.f);
#pragma unroll 8
        for (int a = 0; a < 64; a++) {
            float pa = As[r * PSTR + a];
            float4 m = *(float4*)&Bs[a * PSTR + c4];
            tacc.x += pa * m.x; tacc.y += pa * m.y;
            tacc.z += pa * m.z; tacc.w += pa * m.w;
        }
        __syncthreads();
        *(float4*)&As[r * PSTR + c4] = tacc;
    }
    __syncthreads();

    unsigned ahi[8][4], alo[8][4];
#pragma unroll
    for (int ks = 0; ks < 8; ks++) {
        float a[4];
        a[0] = As[g * PSTR + ks * 8 + t4];
        a[1] = As[(g + 8) * PSTR + ks * 8 + t4];
        a[2] = As[g * PSTR + ks * 8 + t4 + 4];
        a[3] = As[(g + 8) * PSTR + ks * 8 + t4 + 4];
#pragma unroll
        for (int i = 0; i < 4; i++) {
            unsigned h = f2tf(a[i]);
            ahi[ks][i] = h;
            alo[ks][i] = f2tf(a[i] - __uint_as_float(h));
        }
    }

    float acc[8][2][4];
#pragma unroll
    for (int c = 0; c < 8; c++)
#pragma unroll
        for (int nt = 0; nt < 2; nt++)
#pragma unroll
            for (int e = 0; e < 4; e++) acc[c][nt][e] = 0.f;

#pragma unroll 1
    for (int c = 0; c < 8; c++) {
        __syncthreads();
#pragma unroll
        for (int l = 0; l < 8; l++) {
            int idx = l * 256 + tid;
            int row = idx >> 4, f4 = idx & 15;
            float4 v = *(const float4*)&Pp[(size_t)(c * 128 + row) * 64 + f4 * 4];
            *(float4*)&Bs[row * PSTR + f4 * 4] = v;
        }
        __syncthreads();

#pragma unroll
        for (int nt = 0; nt < 2; nt++) {
            int nb = w * 16 + nt * 8 + g;
#pragma unroll
            for (int ks = 0; ks < 8; ks++) {
                float b0 = Bs[nb * PSTR + ks * 8 + t4];
                float b1 = Bs[nb * PSTR + ks * 8 + t4 + 4];
                unsigned bh0 = f2tf(b0), bh1 = f2tf(b1);
                unsigned bl0 = f2tf(b0 - __uint_as_float(bh0));
                unsigned bl1 = f2tf(b1 - __uint_as_float(bh1));
                mma_tf32(acc[c][nt], ahi[ks], bh0, bh1);
                mma_tf32(acc[c][nt], ahi[ks], bl0, bl1);
                mma_tf32(acc[c][nt], alo[ks], bh0, bh1);
            }
        }
    }

    // ---- softmax over full rows ----
    const float SC = 0.125f;
    float mr0 = -1e30f, mr1 = -1e30f;
#pragma unroll
    for (int c = 0; c < 8; c++)
#pragma unroll
        for (int nt = 0; nt < 2; nt++) {
            mr0 = fmaxf(mr0, fmaxf(acc[c][nt][0], acc[c][nt][1]));
            mr1 = fmaxf(mr1, fmaxf(acc[c][nt][2], acc[c][nt][3]));
        }
#pragma unroll
    for (int o = 1; o <= 2; o <<= 1) {
        mr0 = fmaxf(mr0, __shfl_xor_sync(0xffffffffu, mr0, o));
        mr1 = fmaxf(mr1, __shfl_xor_sync(0xffffffffu, mr1, o));
    }
    if (t4 == 0) { wmax[w][g] = mr0; wmax[w][g + 8] = mr1; }
    __syncthreads();
    float M0 = -1e30f, M1 = -1e30f;
#pragma unroll
    for (int ww = 0; ww < 8; ww++) {
        M0 = fmaxf(M0, wmax[ww][g]);
        M1 = fmaxf(M1, wmax[ww][g + 8]);
    }

    float s0 = 0.f, s1 = 0.f;
#pragma unroll
    for (int c = 0; c < 8; c++)
#pragma unroll
        for (int nt = 0; nt < 2; nt++) {
            float e0 = __expf((acc[c][nt][0] - M0) * SC);
            float e1 = __expf((acc[c][nt][1] - M0) * SC);
            float e2 = __expf((acc[c][nt][2] - M1) * SC);
            float e3 = __expf((acc[c][nt][3] - M1) * SC);
            acc[c][nt][0] = e0; acc[c][nt][1] = e1;
            acc[c][nt][2] = e2; acc[c][nt][3] = e3;
            s0 += e0 + e1; s1 += e2 + e3;
        }
#pragma unroll
    for (int o = 1; o <= 2; o <<= 1) {
        s0 += __shfl_xor_sync(0xffffffffu, s0, o);
        s1 += __shfl_xor_sync(0xffffffffu, s1, o);
    }
    if (t4 == 0) { wsum[w][g] = s0; wsum[w][g + 8] = s1; }
    __syncthreads();
    float S0 = 0.f, S1 = 0.f;
#pragma unroll
    for (int ww = 0; ww < 8; ww++) { S0 += wsum[ww][g]; S1 += wsum[ww][g + 8]; }
    float inv0 = 1.0f / S0, inv1 = 1.0f / S1;

#pragma unroll
    for (int c = 0; c < 8; c++)
#pragma unroll
        for (int nt = 0; nt < 2; nt++) {
            int col = c * 128 + w * 16 + nt * 8 + 2 * t4;
            __stcs((float2*)&Op[(size_t)g * SDIM + col],
                   make_float2(acc[c][nt][0] * inv0, acc[c][nt][1] * inv0));
            __stcs((float2*)&Op[(size_t)(g + 8) * SDIM + col],
                   make_float2(acc[c][nt][2] * inv1, acc[c][nt][3] * inv1));
        }
}

// ---------------- V transpose + bf16 split: vT[bh][d][s] -----------------
__global__ void vt_kernel()
{
    __shared__ float ts[64][65];
    int bh = blockIdx.y;
    int s0 = blockIdx.x * 64;
    int tid = threadIdx.x;
#pragma unroll
    for (int l = 0; l < 4; l++) {
        int idx = l * 256 + tid;
        int s = idx >> 4, f4 = idx & 15;
        float4 v = *(const float4*)&g_v[((size_t)bh * SDIM + s0 + s) * DDIM + f4 * 4];
        ts[s][f4 * 4 + 0] = v.x; ts[s][f4 * 4 + 1] = v.y;
        ts[s][f4 * 4 + 2] = v.z; ts[s][f4 * 4 + 3] = v.w;
    }
    __syncthreads();
#pragma unroll
    for (int l = 0; l < 4; l++) {
        int idx = l * 256 + tid;
        int d = idx >> 4, sg = (idx & 15) * 4;
        float x0 = ts[sg + 0][d], x1 = ts[sg + 1][d];
        float x2 = ts[sg + 2][d], x3 = ts[sg + 3][d];
        bf16 h0 = __float2bfloat16_rn(x0), h1 = __float2bfloat16_rn(x1);
        bf16 h2 = __float2bfloat16_rn(x2), h3 = __float2bfloat16_rn(x3);
        size_t o = ((size_t)bh * DDIM + d) * SDIM + s0 + sg;
        *(bf162*)&g_vth[o]     = bf162(h0, h1);
        *(bf162*)&g_vth[o + 2] = bf162(h2, h3);
        *(bf162*)&g_vtl[o] = bf162(__float2bfloat16_rn(x0 - __bfloat162float(h0)),
                                   __float2bfloat16_rn(x1 - __bfloat162float(h1)));
        *(bf162*)&g_vtl[o + 2] = bf162(__float2bfloat16_rn(x2 - __bfloat162float(h2)),
                                       __float2bfloat16_rn(x3 - __bfloat162float(h3)));
    }
}

// ---------------- AV: values = attn @ V, bf16 split-3 TC ------------------
__global__ void __launch_bounds__(256, 1) av_tc_kernel(const float* __restrict__ attn)
{
    __shared__ bf16 Ah[128 * LDSS];
    __shared__ bf16 Al[128 * LDSS];
    __shared__ bf16 Bh[64 * LDSS];
    __shared__ bf16 Bl[64 * LDSS];

    const int bh = blockIdx.y;
    const int bb = bh >> 4, h = bh & 15;
    const int m0 = blockIdx.x * 128;
    const int tid = threadIdx.x, lane = tid & 31, w = tid >> 5;
    const int wm = w * 16;

    const float* Ap = attn + ((size_t)bh << 20) + (size_t)m0 * SDIM;
    const bf16* vhp = g_vth + (size_t)bh * DDIM * SDIM;
    const bf16* vlp = g_vtl + (size_t)bh * DDIM * SDIM;

    unsigned aoH, aoL, boH[4], boL[4];
    {
        int ar = lane & 15, ak = (lane >> 4) * 8;
        aoH = s2u(Ah) + ((wm + ar) * LDSS + ak) * 2;
        aoL = s2u(Al) + ((wm + ar) * LDSS + ak) * 2;
        int nr = (lane & 7) + ((lane >> 4) & 1) * 8;
        int nk = ((lane >> 3) & 1) * 8;
#pragma unroll
        for (int np = 0; np < 4; np++) {
            boH[np] = s2u(Bh) + ((np * 16 + nr) * LDSS + nk) * 2;
            boL[np] = s2u(Bl) + ((np * 16 + nr) * LDSS + nk) * 2;
        }
    }

    float acc[8][4];
#pragma unroll
    for (int i = 0; i < 8; i++)
#pragma unroll
        for (int e = 0; e < 4; e++) acc[i][e] = 0.f;

#pragma unroll 1
    for (int k0 = 0; k0 < SDIM; k0 += 32) {
#pragma unroll
        for (int l = 0; l < 4; l++) {
            int idx = l * 256 + tid;
            int m = idx >> 3, kq = (idx & 7) * 4;
            float4 v = __ldcs((const float4*)&Ap[(size_t)m * SDIM + k0 + kq]);
            int o = m * LDSS + kq;
            bf16 h0 = __float2bfloat16_rn(v.x), h1 = __float2bfloat16_rn(v.y);
            bf16 h2 = __float2bfloat16_rn(v.z), h3 = __float2bfloat16_rn(v.w);
            *(bf162*)&Ah[o]     = bf162(h0, h1);
            *(bf162*)&Ah[o + 2] = bf162(h2, h3);
            *(bf162*)&Al[o] = bf162(__float2bfloat16_rn(v.x - __bfloat162float(h0)),
                                    __float2bfloat16_rn(v.y - __bfloat162float(h1)));
            *(bf162*)&Al[o + 2] = bf162(__float2bfloat16_rn(v.z - __bfloat162float(h2)),
                                        __float2bfloat16_rn(v.w - __bfloat162float(h3)));
        }
        {
            int d = tid >> 2, kq = (tid & 3) * 8;
            uint4 hv = *(const uint4*)&vhp[(size_t)d * SDIM + k0 + kq];
            *(uint4*)&Bh[d * LDSS + kq] = hv;
            uint4 lv = *(const uint4*)&vlp[(size_t)d * SDIM + k0 + kq];
            *(uint4*)&Bl[d * LDSS + kq] = lv;
        }
        __syncthreads();

#pragma unroll
        for (int ks = 0; ks < 2; ks++) {
            unsigned off = ks * 32;
            unsigned ah[4], al[4], bhf[8][2], blf[8][2];
            ldsm4(ah, aoH + off);
            ldsm4(al, aoL + off);
#pragma unroll
            for (int np = 0; np < 4; np++) {
                unsigned r[4];
                ldsm4(r, boH[np] + off);
                bhf[2 * np][0] = r[0]; bhf[2 * np][1] = r[1];
                bhf[2 * np + 1][0] = r[2]; bhf[2 * np + 1][1] = r[3];
                ldsm4(r, boL[np] + off);
                blf[2 * np][0] = r[0]; blf[2 * np][1] = r[1];
                blf[2 * np + 1][0] = r[2]; blf[2 * np + 1][1] = r[3];
            }
#pragma unroll
            for (int nt = 0; nt < 8; nt++) {
                mma16816(acc[nt], ah, bhf[nt]);
                mma16816(acc[nt], ah, blf[nt]);
                mma16816(acc[nt], al, bhf[nt]);
            }
        }
        __syncthreads();
    }

    const int g = lane >> 2, cq = (lane & 3) * 2;
#pragma unroll
    for (int nt = 0; nt < 8; nt++) {
        int d = nt * 8 + cq;
        int r0 = m0 + wm + g;
        *(float2*)&g_val[((size_t)(bb * SDIM + r0)) * EDIM + h * DDIM + d] =
            make_float2(acc[nt][0], acc[nt][1]);
        *(float2*)&g_val[((size_t)(bb * SDIM + r0 + 8)) * EDIM + h * DDIM + d] =
            make_float2(acc[nt][2], acc[nt][3]);
    }
}

// ---------------- launch ----------------------------------------------
extern "C" void kernel_launch(void* const* d_in, const int* in_sizes, int n_in,
                              void* d_out, int out_size)
{
    const float* x  = (const float*)d_in[0];
    const float* W0 = (const float*)d_in[1];
    const float* b0 = (const float*)d_in[2];
    const float* W1 = (const float*)d_in[3];
    const float* b1 = (const float*)d_in[4];
    const float* W2 = (const float*)d_in[5];
    const float* b2 = (const float*)d_in[6];
    const float* Wv = (const float*)d_in[7];
    const float* bv = (const float*)d_in[8];
    const float* Wo = (const float*)d_in[9];
    const float* bo = (const float*)d_in[10];
    const float* A  = (const float*)d_in[11];

    float* out  = (float*)d_out;
    float* attn = out + (size_t)MTOT * EDIM;

    xsum_kernel<<<dim3(4, 4), 256>>>(x);
    gemm_proj_kernel<<<dim3(8, 32, 3), 256>>>(x, W0, b0, W1, b1, Wv, bv);

    s2small_kernel<<<dim3(128, 4), 256>>>(W2, b2);
    m_kernel<<<dim3(64, BH), 64>>>(A);
    vt_kernel<<<dim3(16, BH), 256>>>();

    lsm_kernel<<<dim3(64, BH), 256>>>(attn);
    av_tc_kernel<<<dim3(8, BH), 256>>>(attn);

    gemm_out_kernel<<<dim3(8, 32), 256>>>(Wo, bo, out);
}

// round 7
// speedup vs baseline: 2.1666x; 1.0737x over previous
#include <cuda_runtime.h>
#include <cuda_bf16.h>
#include <cuda_fp16.h>
#include <math.h>

#define SDIM 1024
#define EDIM 1024
#define BDIM 4
#define HDIM 16
#define DDIM 64
#define BH   64
#define MTOT 4096

typedef __nv_bfloat16  bf16;
typedef __nv_bfloat162 bf162;

// ---------------- scratch (device globals; no allocation) ----------------
__device__ float g_p0[BH * SDIM * DDIM];
__device__ float g_p1[BH * SDIM * DDIM];
__device__ float g_v [BH * SDIM * DDIM];
__device__ float g_s2[BDIM * EDIM];
__device__ float g_M [BH * DDIM * DDIM];
__device__ float g_xsum[BDIM * EDIM];
__device__ float g_val[MTOT * EDIM];
__device__ __half g_vth[BH * DDIM * SDIM], g_vtl[BH * DDIM * SDIM];

// ---------------- helpers -------------------------------------------------
__device__ __forceinline__ unsigned s2u(const void* p) {
    return (unsigned)__cvta_generic_to_shared(p);
}
__device__ __forceinline__ void ldsm4(unsigned* r, unsigned addr) {
    asm volatile("ldmatrix.sync.aligned.m8n8.x4.shared.b16 {%0,%1,%2,%3}, [%4];"
                 : "=r"(r[0]), "=r"(r[1]), "=r"(r[2]), "=r"(r[3]) : "r"(addr));
}
__device__ __forceinline__ void mma16816(float* c, const unsigned* a, const unsigned* b) {
    asm volatile("mma.sync.aligned.m16n8k16.row.col.f32.bf16.bf16.f32 "
                 "{%0,%1,%2,%3}, {%4,%5,%6,%7}, {%8,%9}, {%0,%1,%2,%3};"
                 : "+f"(c[0]), "+f"(c[1]), "+f"(c[2]), "+f"(c[3])
                 : "r"(a[0]), "r"(a[1]), "r"(a[2]), "r"(a[3]), "r"(b[0]), "r"(b[1]));
}
__device__ __forceinline__ void mma16816h(float* c, const unsigned* a, const unsigned* b) {
    asm volatile("mma.sync.aligned.m16n8k16.row.col.f32.f16.f16.f32 "
                 "{%0,%1,%2,%3}, {%4,%5,%6,%7}, {%8,%9}, {%0,%1,%2,%3};"
                 : "+f"(c[0]), "+f"(c[1]), "+f"(c[2]), "+f"(c[3])
                 : "r"(a[0]), "r"(a[1]), "r"(a[2]), "r"(a[3]), "r"(b[0]), "r"(b[1]));
}
__device__ __forceinline__ void mma_tf32(float* c, const unsigned* a, unsigned b0, unsigned b1) {
    asm volatile("mma.sync.aligned.m16n8k8.row.col.f32.tf32.tf32.f32 "
                 "{%0,%1,%2,%3}, {%4,%5,%6,%7}, {%8,%9}, {%0,%1,%2,%3};"
                 : "+f"(c[0]), "+f"(c[1]), "+f"(c[2]), "+f"(c[3])
                 : "r"(a[0]), "r"(a[1]), "r"(a[2]), "r"(a[3]), "r"(b0), "r"(b1));
}
__device__ __forceinline__ unsigned f2tf(float x) {
    unsigned r;
    asm("cvt.rna.tf32.f32 %0, %1;" : "=r"(r) : "f"(x));
    return r;
}

// ---------------- xsum[b][e] = sum_s x[b,s,e] -----------------------------
__global__ void xsum_kernel(const float* __restrict__ X)
{
    int b = blockIdx.y;
    int e = blockIdx.x * 256 + threadIdx.x;
    const float* p = X + ((size_t)b * SDIM) * EDIM + e;
    float acc = 0.f;
    for (int s = 0; s < SDIM; s++) acc += p[(size_t)s * EDIM];
    g_xsum[b * EDIM + e] = acc;
}

// ---------------- s2[b*1024+col] = xsum[b] . W2[col] + 1024*b2[col] -------
__global__ void s2small_kernel(const float* __restrict__ W2, const float* __restrict__ b2)
{
    int w = threadIdx.x >> 5, lane = threadIdx.x & 31;
    int b = blockIdx.y;
    int col = blockIdx.x * 8 + w;
    const float* wp = W2 + (size_t)col * EDIM;
    const float* xp = g_xsum + b * EDIM;
    float acc = 0.f;
    for (int e = lane; e < EDIM; e += 32) acc += xp[e] * wp[e];
#pragma unroll
    for (int o = 16; o > 0; o >>= 1) acc += __shfl_xor_sync(0xffffffffu, acc, o);
    if (lane == 0) g_s2[b * EDIM + col] = acc + 1024.0f * b2[col];
}

// ---------------- M[bh,(a,c)] = sum_d A[(a,c),d]*s2[bh,d] -----------------
// tiled: 64 blocks x 256 threads; block handles 64 A-rows for all 64 bh.
__global__ void __launch_bounds__(256) m_kernel(const float* __restrict__ A)
{
    __shared__ float s2s[64][68];
    __shared__ float As[64][68];
    const int tid = threadIdx.x;
    const int r0 = blockIdx.x * 64;

    for (int i = tid; i < 1024; i += 256) {
        int r = i >> 4, c4 = (i & 15) * 4;
        float4 v = *(const float4*)&g_s2[(r >> 4) * EDIM + (r & 15) * 64 + c4];
        *(float4*)&s2s[r][c4] = v;
    }
    for (int i = tid; i < 1024; i += 256) {
        int r = i >> 4, c4 = (i & 15) * 4;
        float4 v = *(const float4*)&A[(size_t)(r0 + r) * 64 + c4];
        *(float4*)&As[r][c4] = v;
    }
    __syncthreads();

    const int row = tid & 63, bh0 = (tid >> 6) * 16;
    float acc[16];
#pragma unroll
    for (int j = 0; j < 16; j++) acc[j] = 0.f;
#pragma unroll
    for (int d4 = 0; d4 < 16; d4++) {
        float4 a = *(float4*)&As[row][d4 * 4];
#pragma unroll
        for (int j = 0; j < 16; j++) {
            float4 s = *(float4*)&s2s[bh0 + j][d4 * 4];
            acc[j] += a.x * s.x + a.y * s.y + a.z * s.z + a.w * s.w;
        }
    }
#pragma unroll
    for (int j = 0; j < 16; j++)
        g_M[(size_t)(bh0 + j) * 4096 + r0 + row] = acc[j];
}

// ---------------- proven tensor-core NT GEMM (bf16 split-3) ---------------
#define KT    32
#define LDSS  40

template <int MODE>
__device__ __forceinline__ void gemm_core(
    const float* __restrict__ X, const float* __restrict__ W,
    const float* __restrict__ bias, float* __restrict__ Out)
{
    __shared__ bf16 Ah[128 * LDSS];
    __shared__ bf16 Al[128 * LDSS];
    __shared__ bf16 Bh[128 * LDSS];
    __shared__ bf16 Bl[128 * LDSS];

    const int tid  = threadIdx.x;
    const int lane = tid & 31;
    const int wid  = tid >> 5;
    const int m0 = blockIdx.y * 128;
    const int n0 = blockIdx.x * 128;
    const int wm = (wid >> 2) * 64;
    const int wn = (wid & 3) * 32;

    float4 pa[4], pb[4];

    unsigned baA[4], baAl[4], baB[2], baBl[2];
    {
        int ar = lane & 15, ak = (lane >> 4) * 8;
#pragma unroll
        for (int mi = 0; mi < 4; mi++) {
            int off = ((wm + mi * 16 + ar) * LDSS + ak) * 2;
            baA[mi]  = s2u(Ah) + off;
            baAl[mi] = s2u(Al) + off;
        }
        int nr = (lane & 7) + ((lane >> 4) & 1) * 8;
        int nk = ((lane >> 3) & 1) * 8;
#pragma unroll
        for (int np = 0; np < 2; np++) {
            int off = ((wn + np * 16 + nr) * LDSS + nk) * 2;
            baB[np]  = s2u(Bh) + off;
            baBl[np] = s2u(Bl) + off;
        }
    }

    float acc[4][4][4];
#pragma unroll
    for (int i = 0; i < 4; i++)
#pragma unroll
        for (int j = 0; j < 4; j++)
#pragma unroll
            for (int e = 0; e < 4; e++) acc[i][j][e] = 0.f;

    auto loadTile = [&](int k0) {
#pragma unroll
        for (int l = 0; l < 4; l++) {
            int idx = l * 256 + tid;
            int row = idx >> 3, kq = (idx & 7) * 4;
            pa[l] = *(const float4*)&X[(size_t)(m0 + row) * EDIM + k0 + kq];
            pb[l] = *(const float4*)&W[(size_t)(n0 + row) * EDIM + k0 + kq];
        }
    };
    auto storeTile = [&]() {
#pragma unroll
        for (int l = 0; l < 4; l++) {
            int idx = l * 256 + tid;
            int row = idx >> 3, kq = (idx & 7) * 4;
            int o = row * LDSS + kq;
            float4 a = pa[l];
            bf16 hx = __float2bfloat16_rn(a.x);
            bf16 hy = __float2bfloat16_rn(a.y);
            bf16 hz = __float2bfloat16_rn(a.z);
            bf16 hw = __float2bfloat16_rn(a.w);
            *(bf162*)&Ah[o]     = bf162(hx, hy);
            *(bf162*)&Ah[o + 2] = bf162(hz, hw);
            *(bf162*)&Al[o]     = bf162(
                __float2bfloat16_rn(a.x - __bfloat162float(hx)),
                __float2bfloat16_rn(a.y - __bfloat162float(hy)));
            *(bf162*)&Al[o + 2] = bf162(
                __float2bfloat16_rn(a.z - __bfloat162float(hz)),
                __float2bfloat16_rn(a.w - __bfloat162float(hw)));
            float4 b = pb[l];
            hx = __float2bfloat16_rn(b.x); hy = __float2bfloat16_rn(b.y);
            hz = __float2bfloat16_rn(b.z); hw = __float2bfloat16_rn(b.w);
            *(bf162*)&Bh[o]     = bf162(hx, hy);
            *(bf162*)&Bh[o + 2] = bf162(hz, hw);
            *(bf162*)&Bl[o]     = bf162(
                __float2bfloat16_rn(b.x - __bfloat162float(hx)),
                __float2bfloat16_rn(b.y - __bfloat162float(hy)));
            *(bf162*)&Bl[o + 2] = bf162(
                __float2bfloat16_rn(b.z - __bfloat162float(hz)),
                __float2bfloat16_rn(b.w - __bfloat162float(hw)));
        }
    };

    loadTile(0);
    storeTile();
    __syncthreads();

    for (int kt = 0; kt < EDIM / KT; kt++) {
        bool has_next = (kt + 1) < EDIM / KT;
        if (has_next) loadTile((kt + 1) * KT);

#pragma unroll
        for (int kk = 0; kk < 2; kk++) {
            unsigned boff = kk * 32;
            unsigned ah[4][4], al[4][4], bh_[4][2], bl_[4][2];
#pragma unroll
            for (int mi = 0; mi < 4; mi++) ldsm4(ah[mi], baA[mi] + boff);
#pragma unroll
            for (int np = 0; np < 2; np++) {
                unsigned r[4];
                ldsm4(r, baB[np] + boff);
                bh_[2 * np][0] = r[0]; bh_[2 * np][1] = r[1];
                bh_[2 * np + 1][0] = r[2]; bh_[2 * np + 1][1] = r[3];
            }
#pragma unroll
            for (int mi = 0; mi < 4; mi++)
#pragma unroll
                for (int ni = 0; ni < 4; ni++) mma16816(acc[mi][ni], ah[mi], bh_[ni]);

#pragma unroll
            for (int np = 0; np < 2; np++) {
                unsigned r[4];
                ldsm4(r, baBl[np] + boff);
                bl_[2 * np][0] = r[0]; bl_[2 * np][1] = r[1];
                bl_[2 * np + 1][0] = r[2]; bl_[2 * np + 1][1] = r[3];
            }
#pragma unroll
            for (int mi = 0; mi < 4; mi++)
#pragma unroll
                for (int ni = 0; ni < 4; ni++) mma16816(acc[mi][ni], ah[mi], bl_[ni]);

#pragma unroll
            for (int mi = 0; mi < 4; mi++) ldsm4(al[mi], baAl[mi] + boff);
#pragma unroll
            for (int mi = 0; mi < 4; mi++)
#pragma unroll
                for (int ni = 0; ni < 4; ni++) mma16816(acc[mi][ni], al[mi], bh_[ni]);
        }

        __syncthreads();
        if (has_next) {
            storeTile();
            __syncthreads();
        }
    }

    const int g = lane >> 2;
    const int cq = (lane & 3) * 2;
#pragma unroll
    for (int mi = 0; mi < 4; mi++) {
#pragma unroll
        for (int ni = 0; ni < 4; ni++) {
            int col = n0 + wn + ni * 8 + cq;
            float2 bia = *(const float2*)&bias[col];
#pragma unroll
            for (int half = 0; half < 2; half++) {
                int row = m0 + wm + mi * 16 + g + half * 8;
                float v0 = acc[mi][ni][half * 2 + 0] + bia.x;
                float v1 = acc[mi][ni][half * 2 + 1] + bia.y;
                if (MODE == 0) {
                    int bb = row >> 10, ss = row & 1023;
                    int h = col >> 6, d = col & 63;
                    *(float2*)&Out[(((size_t)(bb * HDIM + h) * SDIM) + ss) * DDIM + d]
                        = make_float2(v0, v1);
                } else {
                    *(float2*)&Out[(size_t)row * EDIM + col] = make_float2(v0, v1);
                }
            }
        }
    }
}

__global__ void __launch_bounds__(256, 1) gemm_proj_kernel(
    const float* __restrict__ X,
    const float* __restrict__ W0, const float* __restrict__ b0,
    const float* __restrict__ W1, const float* __restrict__ b1,
    const float* __restrict__ Wv, const float* __restrict__ bv)
{
    switch (blockIdx.z) {
        case 0:  gemm_core<0>(X, W0, b0, g_p0); break;
        case 1:  gemm_core<0>(X, W1, b1, g_p1); break;
        default: gemm_core<0>(X, Wv, bv, g_v);  break;
    }
}

__global__ void __launch_bounds__(256, 1) gemm_out_kernel(
    const float* __restrict__ Wo, const float* __restrict__ bo, float* __restrict__ Out)
{
    gemm_core<1>(g_val, Wo, bo, Out);
}

// ---------------- fused t-compute + logits (3xtf32) + softmax -------------
#define PSTR 68

__global__ void __launch_bounds__(256, 1) lsm_kernel(float* __restrict__ attn)
{
    __shared__ float Bs[128 * PSTR];
    __shared__ float As[16 * PSTR];
    __shared__ float wmax[8][16];
    __shared__ float wsum[8][16];

    const int bh = blockIdx.y;
    const int m0 = blockIdx.x * 16;
    const int tid = threadIdx.x, lane = tid & 31, w = tid >> 5;
    const int g = lane >> 2, t4 = lane & 3;

    const float* Pp = g_p1 + (size_t)bh * SDIM * DDIM;
    float* Op = attn + ((size_t)bh << 20) + (size_t)m0 * SDIM;

    // ---- prologue: t = p0_tile(16x64) @ M(64x64), M staged through Bs ----
    {
        const float* Mp = g_M + (size_t)bh * 4096;
#pragma unroll
        for (int l = 0; l < 4; l++) {
            int idx = l * 256 + tid;
            int row = idx >> 4, c4 = (idx & 15) * 4;
            *(float4*)&Bs[row * PSTR + c4] = *(const float4*)&Mp[row * 64 + c4];
        }
        const float* P0p = g_p0 + ((size_t)bh * SDIM + m0) * DDIM;
        int r = tid >> 4, f4 = (tid & 15) * 4;
        *(float4*)&As[r * PSTR + f4] = *(const float4*)&P0p[r * 64 + f4];
    }
    __syncthreads();
    {
        int r = tid >> 4, c4 = (tid & 15) * 4;
        float4 tacc = make_float4(0.f, 0.f, 0.f, 0.f);
#pragma unroll 8
        for (int a = 0; a < 64; a++) {
            float pa = As[r * PSTR + a];
            float4 m = *(float4*)&Bs[a * PSTR + c4];
            tacc.x += pa * m.x; tacc.y += pa * m.y;
            tacc.z += pa * m.z; tacc.w += pa * m.w;
        }
        __syncthreads();
        *(float4*)&As[r * PSTR + c4] = tacc;
    }
    __syncthreads();

    unsigned ahi[8][4], alo[8][4];
#pragma unroll
    for (int ks = 0; ks < 8; ks++) {
        float a[4];
        a[0] = As[g * PSTR + ks * 8 + t4];
        a[1] = As[(g + 8) * PSTR + ks * 8 + t4];
        a[2] = As[g * PSTR + ks * 8 + t4 + 4];
        a[3] = As[(g + 8) * PSTR + ks * 8 + t4 + 4];
#pragma unroll
        for (int i = 0; i < 4; i++) {
            unsigned h = f2tf(a[i]);
            ahi[ks][i] = h;
            alo[ks][i] = f2tf(a[i] - __uint_as_float(h));
        }
    }

    float acc[8][2][4];
#pragma unroll
    for (int c = 0; c < 8; c++)
#pragma unroll
        for (int nt = 0; nt < 2; nt++)
#pragma unroll
            for (int e = 0; e < 4; e++) acc[c][nt][e] = 0.f;

#pragma unroll 1
    for (int c = 0; c < 8; c++) {
        __syncthreads();
#pragma unroll
        for (int l = 0; l < 8; l++) {
            int idx = l * 256 + tid;
            int row = idx >> 4, f4 = idx & 15;
            float4 v = *(const float4*)&Pp[(size_t)(c * 128 + row) * 64 + f4 * 4];
            *(float4*)&Bs[row * PSTR + f4 * 4] = v;
        }
        __syncthreads();

#pragma unroll
        for (int nt = 0; nt < 2; nt++) {
            int nb = w * 16 + nt * 8 + g;
#pragma unroll
            for (int ks = 0; ks < 8; ks++) {
                float b0 = Bs[nb * PSTR + ks * 8 + t4];
                float b1 = Bs[nb * PSTR + ks * 8 + t4 + 4];
                unsigned bh0 = f2tf(b0), bh1 = f2tf(b1);
                unsigned bl0 = f2tf(b0 - __uint_as_float(bh0));
                unsigned bl1 = f2tf(b1 - __uint_as_float(bh1));
                mma_tf32(acc[c][nt], ahi[ks], bh0, bh1);
                mma_tf32(acc[c][nt], ahi[ks], bl0, bl1);
                mma_tf32(acc[c][nt], alo[ks], bh0, bh1);
            }
        }
    }

    // ---- softmax over full rows ----
    const float SC = 0.125f;
    float mr0 = -1e30f, mr1 = -1e30f;
#pragma unroll
    for (int c = 0; c < 8; c++)
#pragma unroll
        for (int nt = 0; nt < 2; nt++) {
            mr0 = fmaxf(mr0, fmaxf(acc[c][nt][0], acc[c][nt][1]));
            mr1 = fmaxf(mr1, fmaxf(acc[c][nt][2], acc[c][nt][3]));
        }
#pragma unroll
    for (int o = 1; o <= 2; o <<= 1) {
        mr0 = fmaxf(mr0, __shfl_xor_sync(0xffffffffu, mr0, o));
        mr1 = fmaxf(mr1, __shfl_xor_sync(0xffffffffu, mr1, o));
    }
    if (t4 == 0) { wmax[w][g] = mr0; wmax[w][g + 8] = mr1; }
    __syncthreads();
    float M0 = -1e30f, M1 = -1e30f;
#pragma unroll
    for (int ww = 0; ww < 8; ww++) {
        M0 = fmaxf(M0, wmax[ww][g]);
        M1 = fmaxf(M1, wmax[ww][g + 8]);
    }

    float s0 = 0.f, s1 = 0.f;
#pragma unroll
    for (int c = 0; c < 8; c++)
#pragma unroll
        for (int nt = 0; nt < 2; nt++) {
            float e0 = __expf((acc[c][nt][0] - M0) * SC);
            float e1 = __expf((acc[c][nt][1] - M0) * SC);
            float e2 = __expf((acc[c][nt][2] - M1) * SC);
            float e3 = __expf((acc[c][nt][3] - M1) * SC);
            acc[c][nt][0] = e0; acc[c][nt][1] = e1;
            acc[c][nt][2] = e2; acc[c][nt][3] = e3;
            s0 += e0 + e1; s1 += e2 + e3;
        }
#pragma unroll
    for (int o = 1; o <= 2; o <<= 1) {
        s0 += __shfl_xor_sync(0xffffffffu, s0, o);
        s1 += __shfl_xor_sync(0xffffffffu, s1, o);
    }
    if (t4 == 0) { wsum[w][g] = s0; wsum[w][g + 8] = s1; }
    __syncthreads();
    float S0 = 0.f, S1 = 0.f;
#pragma unroll
    for (int ww = 0; ww < 8; ww++) { S0 += wsum[ww][g]; S1 += wsum[ww][g + 8]; }
    float inv0 = 1.0f / S0, inv1 = 1.0f / S1;

#pragma unroll
    for (int c = 0; c < 8; c++)
#pragma unroll
        for (int nt = 0; nt < 2; nt++) {
            int col = c * 128 + w * 16 + nt * 8 + 2 * t4;
            __stcs((float2*)&Op[(size_t)g * SDIM + col],
                   make_float2(acc[c][nt][0] * inv0, acc[c][nt][1] * inv0));
            __stcs((float2*)&Op[(size_t)(g + 8) * SDIM + col],
                   make_float2(acc[c][nt][2] * inv1, acc[c][nt][3] * inv1));
        }
}

// ---------------- V transpose + fp16 split: vT[bh][d][s] ------------------
__global__ void vt_kernel()
{
    __shared__ float ts[64][65];
    int bh = blockIdx.y;
    int s0 = blockIdx.x * 64;
    int tid = threadIdx.x;
#pragma unroll
    for (int l = 0; l < 4; l++) {
        int idx = l * 256 + tid;
        int s = idx >> 4, f4 = idx & 15;
        float4 v = *(const float4*)&g_v[((size_t)bh * SDIM + s0 + s) * DDIM + f4 * 4];
        ts[s][f4 * 4 + 0] = v.x; ts[s][f4 * 4 + 1] = v.y;
        ts[s][f4 * 4 + 2] = v.z; ts[s][f4 * 4 + 3] = v.w;
    }
    __syncthreads();
#pragma unroll
    for (int l = 0; l < 4; l++) {
        int idx = l * 256 + tid;
        int d = idx >> 4, sg = (idx & 15) * 4;
        float x0 = ts[sg + 0][d], x1 = ts[sg + 1][d];
        float x2 = ts[sg + 2][d], x3 = ts[sg + 3][d];
        __half h0 = __float2half_rn(x0), h1 = __float2half_rn(x1);
        __half h2 = __float2half_rn(x2), h3 = __float2half_rn(x3);
        size_t o = ((size_t)bh * DDIM + d) * SDIM + s0 + sg;
        *(__half2*)&g_vth[o]     = __half2(h0, h1);
        *(__half2*)&g_vth[o + 2] = __half2(h2, h3);
        *(__half2*)&g_vtl[o] = __half2(__float2half_rn(x0 - __half2float(h0)),
                                       __float2half_rn(x1 - __half2float(h1)));
        *(__half2*)&g_vtl[o + 2] = __half2(__float2half_rn(x2 - __half2float(h2)),
                                           __float2half_rn(x3 - __half2float(h3)));
    }
}

// ---------------- AV: values = attn @ V, fp16 2-term TC -------------------
__global__ void __launch_bounds__(256, 1) av_tc_kernel(const float* __restrict__ attn)
{
    __shared__ __half Ah[128 * LDSS];
    __shared__ __half Bh[64 * LDSS];
    __shared__ __half Bl[64 * LDSS];

    const int bh = blockIdx.y;
    const int bb = bh >> 4, h = bh & 15;
    const int m0 = blockIdx.x * 128;
    const int tid = threadIdx.x, lane = tid & 31, w = tid >> 5;
    const int wm = w * 16;

    const float* Ap = attn + ((size_t)bh << 20) + (size_t)m0 * SDIM;
    const __half* vhp = g_vth + (size_t)bh * DDIM * SDIM;
    const __half* vlp = g_vtl + (size_t)bh * DDIM * SDIM;

    unsigned aoH, boH[4], boL[4];
    {
        int ar = lane & 15, ak = (lane >> 4) * 8;
        aoH = s2u(Ah) + ((wm + ar) * LDSS + ak) * 2;
        int nr = (lane & 7) + ((lane >> 4) & 1) * 8;
        int nk = ((lane >> 3) & 1) * 8;
#pragma unroll
        for (int np = 0; np < 4; np++) {
            boH[np] = s2u(Bh) + ((np * 16 + nr) * LDSS + nk) * 2;
            boL[np] = s2u(Bl) + ((np * 16 + nr) * LDSS + nk) * 2;
        }
    }

    float acc[8][4];
#pragma unroll
    for (int i = 0; i < 8; i++)
#pragma unroll
        for (int e = 0; e < 4; e++) acc[i][e] = 0.f;

#pragma unroll 1
    for (int k0 = 0; k0 < SDIM; k0 += 32) {
#pragma unroll
        for (int l = 0; l < 4; l++) {
            int idx = l * 256 + tid;
            int m = idx >> 3, kq = (idx & 7) * 4;
            float4 v = __ldcs((const float4*)&Ap[(size_t)m * SDIM + k0 + kq]);
            int o = m * LDSS + kq;
            *(__half2*)&Ah[o]     = __floats2half2_rn(v.x, v.y);
            *(__half2*)&Ah[o + 2] = __floats2half2_rn(v.z, v.w);
        }
        {
            int d = tid >> 2, kq = (tid & 3) * 8;
            uint4 hv = *(const uint4*)&vhp[(size_t)d * SDIM + k0 + kq];
            *(uint4*)&Bh[d * LDSS + kq] = hv;
            uint4 lv = *(const uint4*)&vlp[(size_t)d * SDIM + k0 + kq];
            *(uint4*)&Bl[d * LDSS + kq] = lv;
        }
        __syncthreads();

#pragma unroll
        for (int ks = 0; ks < 2; ks++) {
            unsigned off = ks * 32;
            unsigned ah[4], bhf[8][2], blf[8][2];
            ldsm4(ah, aoH + off);
#pragma unroll
            for (int np = 0; np < 4; np++) {
                unsigned r[4];
                ldsm4(r, boH[np] + off);
                bhf[2 * np][0] = r[0]; bhf[2 * np][1] = r[1];
                bhf[2 * np + 1][0] = r[2]; bhf[2 * np + 1][1] = r[3];
                ldsm4(r, boL[np] + off);
                blf[2 * np][0] = r[0]; blf[2 * np][1] = r[1];
                blf[2 * np + 1][0] = r[2]; blf[2 * np + 1][1] = r[3];
            }
#pragma unroll
            for (int nt = 0; nt < 8; nt++) {
                mma16816h(acc[nt], ah, bhf[nt]);
                mma16816h(acc[nt], ah, blf[nt]);
            }
        }
        __syncthreads();
    }

    const int g = lane >> 2, cq = (lane & 3) * 2;
#pragma unroll
    for (int nt = 0; nt < 8; nt++) {
        int d = nt * 8 + cq;
        int r0 = m0 + wm + g;
        *(float2*)&g_val[((size_t)(bb * SDIM + r0)) * EDIM + h * DDIM + d] =
            make_float2(acc[nt][0], acc[nt][1]);
        *(float2*)&g_val[((size_t)(bb * SDIM + r0 + 8)) * EDIM + h * DDIM + d] =
            make_float2(acc[nt][2], acc[nt][3]);
    }
}

// ---------------- launch ----------------------------------------------
extern "C" void kernel_launch(void* const* d_in, const int* in_sizes, int n_in,
                              void* d_out, int out_size)
{
    const float* x  = (const float*)d_in[0];
    const float* W0 = (const float*)d_in[1];
    const float* b0 = (const float*)d_in[2];
    const float* W1 = (const float*)d_in[3];
    const float* b1 = (const float*)d_in[4];
    const float* W2 = (const float*)d_in[5];
    const float* b2 = (const float*)d_in[6];
    const float* Wv = (const float*)d_in[7];
    const float* bv = (const float*)d_in[8];
    const float* Wo = (const float*)d_in[9];
    const float* bo = (const float*)d_in[10];
    const float* A  = (const float*)d_in[11];

    float* out  = (float*)d_out;
    float* attn = out + (size_t)MTOT * EDIM;

    xsum_kernel<<<dim3(4, 4), 256>>>(x);
    gemm_proj_kernel<<<dim3(8, 32, 3), 256>>>(x, W0, b0, W1, b1, Wv, bv);

    s2small_kernel<<<dim3(128, 4), 256>>>(W2, b2);
    m_kernel<<<64, 256>>>(A);
    vt_kernel<<<dim3(16, BH), 256>>>();

    lsm_kernel<<<dim3(64, BH), 256>>>(attn);
    av_tc_kernel<<<dim3(8, BH), 256>>>(attn);

    gemm_out_kernel<<<dim3(8, 32), 256>>>(Wo, bo, out);
}